// round 2
// baseline (speedup 1.0000x reference)
#include <cuda_runtime.h>
#include <math.h>

// Problem constants (from reference): N=10000, E=40000, IN_CH=256, OUT_CH=256,
// EDGE_DIM=128, NS=64, NV=8, WN1=WN2=5120.

#define MAXN 10000
#define MAXE 40000

// ---------------- scratch (static __device__ — no allocations allowed) -----
__device__ float g_skip[MAXN * 256];
__device__ float g_h   [MAXN * 64];
__device__ float g_u1  [MAXE * 128];
__device__ float g_u2  [MAXE * 128];
__device__ float g_shb [MAXE * 8];     // sh1 (3) + sh2 (5)
__device__ float g_h1  [MAXN * 128];   // msg scatter accum -> h1
__device__ float g_cnt [MAXN];
__device__ float g_h2  [MAXN * 64];
__device__ float g_mu  [64];
__device__ float g_var [64];
__device__ float g_sph [MAXN * 64];

__device__ __forceinline__ float softplusf(float x) {
    // logaddexp(x, 0) = max(x,0) + log1p(exp(-|x|))  (matches jax.nn.softplus)
    return fmaxf(x, 0.0f) + log1pf(expf(-fabsf(x)));
}

// ---------------- generic tiled fp32 GEMM: C = act(A@B + bias) (+ add) -----
// A [M,K] rm, B [K,N] rm. BM=BN=64, BK=16, 256 thr, 4x4 per thread.
template <int ACT, int ADD>
__global__ void __launch_bounds__(256) gemm_kernel(
    const float* __restrict__ A, const float* __restrict__ B,
    const float* __restrict__ bias, const float* __restrict__ addsrc,
    float* __restrict__ C, int M, int N, int K)
{
    __shared__ float As[16][64];
    __shared__ float Bs[16][64];
    const int bm = blockIdx.y * 64, bn = blockIdx.x * 64;
    const int tid = threadIdx.x;
    const int ty = tid >> 4, tx = tid & 15;

    float acc[4][4] = {};
    for (int k0 = 0; k0 < K; k0 += 16) {
#pragma unroll
        for (int l = 0; l < 4; ++l) {
            int idx = tid + l * 256;          // 0..1023
            int r = idx >> 4, c = idx & 15;
            int gr = bm + r;
            As[c][r] = (gr < M) ? A[(size_t)gr * K + k0 + c] : 0.0f;
        }
#pragma unroll
        for (int l = 0; l < 4; ++l) {
            int idx = tid + l * 256;
            int r = idx >> 6, c = idx & 63;
            Bs[r][c] = B[(size_t)(k0 + r) * N + bn + c];
        }
        __syncthreads();
#pragma unroll
        for (int kk = 0; kk < 16; ++kk) {
            float ra[4], rb[4];
#pragma unroll
            for (int a = 0; a < 4; ++a) ra[a] = As[kk][ty * 4 + a];
#pragma unroll
            for (int b = 0; b < 4; ++b) rb[b] = Bs[kk][tx * 4 + b];
#pragma unroll
            for (int a = 0; a < 4; ++a)
#pragma unroll
                for (int b = 0; b < 4; ++b)
                    acc[a][b] = fmaf(ra[a], rb[b], acc[a][b]);
        }
        __syncthreads();
    }
#pragma unroll
    for (int a = 0; a < 4; ++a) {
        int m = bm + ty * 4 + a;
        if (m >= M) continue;
#pragma unroll
        for (int b = 0; b < 4; ++b) {
            int n = bn + tx * 4 + b;
            float v = acc[a][b] + bias[n];
            if (ACT) v = softplusf(v);
            if (ADD) v += addsrc[(size_t)m * N + n];
            C[(size_t)m * N + n] = v;
        }
    }
}

// ---------------- spherical harmonics per edge -----------------------------
__global__ void sh_kernel(const float* __restrict__ ev, int E)
{
    int e = blockIdx.x * blockDim.x + threadIdx.x;
    if (e >= E) return;
    float x = ev[e * 3 + 0], y = ev[e * 3 + 1], z = ev[e * 3 + 2];
    float rn = rsqrtf(x * x + y * y + z * z);
    x *= rn; y *= rn; z *= rn;
    const float s3 = 1.7320508075688772f;
    const float s5 = 2.2360679774997896f;
    float* o = g_shb + (size_t)e * 8;
    o[0] = s3 * x;
    o[1] = s3 * y;
    o[2] = s3 * z;
    o[3] = s5 * s3 * x * z;
    o[4] = s5 * s3 * x * y;
    o[5] = s5 * (y * y - 0.5f * (x * x + z * z));
    o[6] = s5 * s3 * y * z;
    o[7] = s5 * (s3 * 0.5f) * (z * z - x * x);
}

// ---------------- zero scatter buffers --------------------------------------
__global__ void zero_kernel(int Nn)
{
    int t = blockIdx.x * blockDim.x + threadIdx.x;
    int gs = gridDim.x * blockDim.x;
    for (int i = t; i < Nn * 128; i += gs) g_h1[i] = 0.0f;
    for (int i = t; i < Nn * 64;  i += gs) g_h2[i] = 0.0f;
    for (int i = t; i < Nn;       i += gs) g_cnt[i] = 0.0f;
}

// ---------------- fused message pass 1 --------------------------------------
// Per edge: W(5120) = u1 @ fc1_w2 + b2 (never materialized); msg contraction
// with s = h[dst]; atomic scatter into g_h1[src], counts into g_cnt.
__global__ void __launch_bounds__(256) msg1_kernel(
    const int* __restrict__ ei, const float* __restrict__ W2,
    const float* __restrict__ B2, int E)
{
    extern __shared__ float smem[];
    float* su   = smem;              // [64][128]
    float* ss   = su + 64 * 128;     // [64][64]
    float* sw   = ss + 64 * 64;      // [128][64]
    float* macc = sw + 128 * 64;     // [64][80]
    __shared__ int ssrc[64], sdst[64];

    const int tid = threadIdx.x;
    const int e0 = blockIdx.x * 64;
    const int ne = min(64, E - e0);

    if (tid < 64) {
        int ok = tid < ne;
        ssrc[tid] = ok ? ei[e0 + tid] : 0;
        sdst[tid] = ok ? ei[E + e0 + tid] : 0;
    }
    __syncthreads();
    for (int idx = tid; idx < 64 * 128; idx += 256)
        su[idx] = ((idx >> 7) < ne) ? g_u1[(size_t)e0 * 128 + idx] : 0.0f;
    for (int idx = tid; idx < 64 * 64; idx += 256) {
        int e = idx >> 6, i = idx & 63;
        ss[idx] = (e < ne) ? g_h[(size_t)sdst[e] * 64 + i] : 0.0f;
    }
    for (int idx = tid; idx < 64 * 80; idx += 256) macc[idx] = 0.0f;
    __syncthreads();

    const int eg = tid >> 4, qg = tid & 15;
    const int eb = eg * 4, q0 = qg * 4;

    for (int ch = 0; ch < 80; ++ch) {
        // stage weight chunk: sw[d][q] = W2[d, ch*64 + q]
#pragma unroll
        for (int l = 0; l < 8; ++l) {
            int idx = tid + l * 256;                   // 0..2047 (float4 units)
            int d = idx >> 4, q4 = idx & 15;
            reinterpret_cast<float4*>(sw)[d * 16 + q4] =
                reinterpret_cast<const float4*>(W2 + (size_t)d * 5120 + ch * 64)[q4];
        }
        __syncthreads();

        float acc[4][4];
        {
            float bb[4];
#pragma unroll
            for (int b = 0; b < 4; ++b) bb[b] = B2[ch * 64 + q0 + b];
#pragma unroll
            for (int a = 0; a < 4; ++a)
#pragma unroll
                for (int b = 0; b < 4; ++b) acc[a][b] = bb[b];
        }
#pragma unroll 2
        for (int d4 = 0; d4 < 32; ++d4) {
            float4 av[4], bv[4];
#pragma unroll
            for (int a = 0; a < 4; ++a)
                av[a] = *reinterpret_cast<const float4*>(su + (eb + a) * 128 + d4 * 4);
#pragma unroll
            for (int j = 0; j < 4; ++j)
                bv[j] = *reinterpret_cast<const float4*>(sw + (d4 * 4 + j) * 64 + q0);
#pragma unroll
            for (int a = 0; a < 4; ++a) {
                float ax[4] = {av[a].x, av[a].y, av[a].z, av[a].w};
#pragma unroll
                for (int j = 0; j < 4; ++j) {
                    float bx[4] = {bv[j].x, bv[j].y, bv[j].z, bv[j].w};
#pragma unroll
                    for (int b = 0; b < 4; ++b)
                        acc[a][b] = fmaf(ax[j], bx[b], acc[a][b]);
                }
            }
        }

        if (ch < 64) {
            // W0 block: col = i*64 + k, i = ch, k = q
#pragma unroll
            for (int a = 0; a < 4; ++a) {
                float sv = ss[(eb + a) * 64 + ch];
#pragma unroll
                for (int b = 0; b < 4; ++b)
                    macc[(eb + a) * 80 + q0 + b] += sv * acc[a][b];
            }
        } else {
            // W1/W2 blocks: col = 4096(+512) + i*8 + k
            const int base = (ch < 72) ? 64 : 72;
            const int ci = (ch < 72) ? (ch - 64) : (ch - 72);
#pragma unroll
            for (int a = 0; a < 4; ++a)
#pragma unroll
                for (int b = 0; b < 4; ++b) {
                    int q = q0 + b;
                    int i = ci * 8 + (q >> 3);
                    int k = q & 7;
                    atomicAdd(&macc[(eb + a) * 80 + base + k],
                              ss[(eb + a) * 64 + i] * acc[a][b]);
                }
        }
        __syncthreads();
    }

    // epilogue: msg = [o0(64) | o1(8x3) | o2(8x5)] * c, scatter to src
    const float C1 = 0.125f;
    for (int idx = tid; idx < 64 * 128; idx += 256) {
        int e = idx >> 7, col = idx & 127;
        if (e >= ne) continue;
        float val;
        if (col < 64) {
            val = C1 * macc[e * 80 + col];
        } else if (col < 88) {
            int t = col - 64; int k = t / 3, m = t - k * 3;
            val = C1 * macc[e * 80 + 64 + k] * g_shb[(size_t)(e0 + e) * 8 + m];
        } else {
            int t = col - 88; int k = t / 5, m = t - k * 5;
            val = C1 * macc[e * 80 + 72 + k] * g_shb[(size_t)(e0 + e) * 8 + 3 + m];
        }
        atomicAdd(&g_h1[(size_t)ssrc[e] * 128 + col], val);
    }
    if (tid < ne) atomicAdd(&g_cnt[ssrc[tid]], 1.0f);
}

// ---------------- h1 finalize: mean + self term ------------------------------
__global__ void h1_finalize_kernel(int Nn)
{
    int t = blockIdx.x * blockDim.x + threadIdx.x;
    int gs = gridDim.x * blockDim.x;
    for (int idx = t; idx < Nn * 128; idx += gs) {
        int n = idx >> 7, c = idx & 127;
        float cnt = fmaxf(g_cnt[n], 1.0f);
        float v = g_h1[idx] / cnt;
        if (c < 64) v += g_h[n * 64 + c];
        g_h1[idx] = v;
    }
}

// ---------------- fused message pass 2 --------------------------------------
// t[e,k] = sum_{j<80} S[e,j] * (u2 @ fc2_w2 + b2)[e, j*64+k], scatter to src.
__global__ void __launch_bounds__(256) msg2_kernel(
    const int* __restrict__ ei, const float* __restrict__ W2,
    const float* __restrict__ B2, int E)
{
    extern __shared__ float smem[];
    float* su   = smem;              // [64][128] u2
    float* sS   = su + 64 * 128;     // [64][80]
    float* sw   = sS + 64 * 80;      // [128][64] (also staging for he)
    float* tacc = sw + 128 * 64;     // [64][64]
    __shared__ int ssrc[64], sdst[64];

    const int tid = threadIdx.x;
    const int e0 = blockIdx.x * 64;
    const int ne = min(64, E - e0);

    if (tid < 64) {
        int ok = tid < ne;
        ssrc[tid] = ok ? ei[e0 + tid] : 0;
        sdst[tid] = ok ? ei[E + e0 + tid] : 0;
    }
    __syncthreads();
    for (int idx = tid; idx < 64 * 128; idx += 256)
        su[idx] = ((idx >> 7) < ne) ? g_u2[(size_t)e0 * 128 + idx] : 0.0f;
    // stage he = h1[dst] into sw temporarily
    for (int idx = tid; idx < 64 * 128; idx += 256) {
        int e = idx >> 7;
        sw[idx] = (e < ne) ? g_h1[(size_t)sdst[e] * 128 + (idx & 127)] : 0.0f;
    }
    for (int idx = tid; idx < 64 * 64; idx += 256) tacc[idx] = 0.0f;
    __syncthreads();

    const float i3 = 0.5773502691896258f;   // 1/sqrt(3)
    const float i5 = 0.4472135954999579f;   // 1/sqrt(5)
    for (int idx = tid; idx < 64 * 80; idx += 256) {
        int e = idx / 80, j = idx - e * 80;
        const float* he = sw + e * 128;
        float v;
        if (j < 64) {
            v = he[j];
        } else if (j < 72) {
            int i = j - 64;
            float p = 0.0f;
#pragma unroll
            for (int m = 0; m < 3; ++m)
                p += he[64 + i * 3 + m] * g_shb[(size_t)(e0 + e) * 8 + m];
            v = p * i3;
        } else {
            int i = j - 72;
            float p = 0.0f;
#pragma unroll
            for (int m = 0; m < 5; ++m)
                p += he[88 + i * 5 + m] * g_shb[(size_t)(e0 + e) * 8 + 3 + m];
            v = p * i5;
        }
        sS[idx] = v;
    }
    __syncthreads();

    const int eg = tid >> 4, qg = tid & 15;
    const int eb = eg * 4, q0 = qg * 4;

    for (int ch = 0; ch < 80; ++ch) {
#pragma unroll
        for (int l = 0; l < 8; ++l) {
            int idx = tid + l * 256;
            int d = idx >> 4, q4 = idx & 15;
            reinterpret_cast<float4*>(sw)[d * 16 + q4] =
                reinterpret_cast<const float4*>(W2 + (size_t)d * 5120 + ch * 64)[q4];
        }
        __syncthreads();

        float acc[4][4];
        {
            float bb[4];
#pragma unroll
            for (int b = 0; b < 4; ++b) bb[b] = B2[ch * 64 + q0 + b];
#pragma unroll
            for (int a = 0; a < 4; ++a)
#pragma unroll
                for (int b = 0; b < 4; ++b) acc[a][b] = bb[b];
        }
#pragma unroll 2
        for (int d4 = 0; d4 < 32; ++d4) {
            float4 av[4], bv[4];
#pragma unroll
            for (int a = 0; a < 4; ++a)
                av[a] = *reinterpret_cast<const float4*>(su + (eb + a) * 128 + d4 * 4);
#pragma unroll
            for (int j = 0; j < 4; ++j)
                bv[j] = *reinterpret_cast<const float4*>(sw + (d4 * 4 + j) * 64 + q0);
#pragma unroll
            for (int a = 0; a < 4; ++a) {
                float ax[4] = {av[a].x, av[a].y, av[a].z, av[a].w};
#pragma unroll
                for (int j = 0; j < 4; ++j) {
                    float bx[4] = {bv[j].x, bv[j].y, bv[j].z, bv[j].w};
#pragma unroll
                    for (int b = 0; b < 4; ++b)
                        acc[a][b] = fmaf(ax[j], bx[b], acc[a][b]);
                }
            }
        }
#pragma unroll
        for (int a = 0; a < 4; ++a) {
            float sv = sS[(eb + a) * 80 + ch];
#pragma unroll
            for (int b = 0; b < 4; ++b)
                tacc[(eb + a) * 64 + q0 + b] += sv * acc[a][b];
        }
        __syncthreads();
    }

    const float INV = 0.11180339887498948f;  // 1/sqrt(80)
    for (int idx = tid; idx < 64 * 64; idx += 256) {
        int e = idx >> 6;
        if (e < ne)
            atomicAdd(&g_h2[(size_t)ssrc[e] * 64 + (idx & 63)], INV * tacc[idx]);
    }
}

__global__ void h2_finalize_kernel(int Nn)
{
    int t = blockIdx.x * blockDim.x + threadIdx.x;
    int gs = gridDim.x * blockDim.x;
    for (int idx = t; idx < Nn * 64; idx += gs) {
        int n = idx >> 6;
        g_h2[idx] /= fmaxf(g_cnt[n], 1.0f);
    }
}

// ---------------- batch-norm stats (one block per channel) -----------------
__global__ void bn_stats_kernel(int Nn)
{
    __shared__ float rs[256], rs2[256];
    const int c = blockIdx.x;
    float s = 0.0f, s2 = 0.0f;
    for (int n = threadIdx.x; n < Nn; n += 256) {
        float x = g_h2[(size_t)n * 64 + c];
        s += x; s2 += x * x;
    }
    rs[threadIdx.x] = s; rs2[threadIdx.x] = s2;
    __syncthreads();
    for (int off = 128; off > 0; off >>= 1) {
        if (threadIdx.x < off) {
            rs[threadIdx.x]  += rs[threadIdx.x + off];
            rs2[threadIdx.x] += rs2[threadIdx.x + off];
        }
        __syncthreads();
    }
    if (threadIdx.x == 0) {
        float mu = rs[0] / (float)Nn;
        g_mu[c]  = mu;
        g_var[c] = rs2[0] / (float)Nn - mu * mu;
    }
}

__global__ void bn_apply_kernel(const float* __restrict__ gamma,
                                const float* __restrict__ beta, int Nn)
{
    int t = blockIdx.x * blockDim.x + threadIdx.x;
    int gs = gridDim.x * blockDim.x;
    for (int idx = t; idx < Nn * 64; idx += gs) {
        int c = idx & 63;
        float x = (g_h2[idx] - g_mu[c]) * rsqrtf(g_var[c] + 1e-5f) * gamma[c] + beta[c];
        g_sph[idx] = softplusf(x);
    }
}

// ---------------- launch ----------------------------------------------------
extern "C" void kernel_launch(void* const* d_in, const int* in_sizes, int n_in,
                              void* d_out, int out_size)
{
    const float* node_feature = (const float*)d_in[0];
    const int*   edge_index   = (const int*)d_in[1];
    const float* edge_feature = (const float*)d_in[2];
    const float* edge_vec     = (const float*)d_in[3];
    const float* w_node = (const float*)d_in[4];
    const float* b_node = (const float*)d_in[5];
    const float* w_skip = (const float*)d_in[6];
    const float* b_skip = (const float*)d_in[7];
    const float* fc1_w1 = (const float*)d_in[8];
    const float* fc1_b1 = (const float*)d_in[9];
    const float* fc1_w2 = (const float*)d_in[10];
    const float* fc1_b2 = (const float*)d_in[11];
    const float* fc2_w1 = (const float*)d_in[12];
    const float* fc2_b1 = (const float*)d_in[13];
    const float* fc2_w2 = (const float*)d_in[14];
    const float* fc2_b2 = (const float*)d_in[15];
    const float* bn_gamma = (const float*)d_in[16];
    const float* bn_beta  = (const float*)d_in[17];
    const float* w_out = (const float*)d_in[18];
    const float* b_out = (const float*)d_in[19];
    float* out = (float*)d_out;

    const int Nn = in_sizes[0] / 256;   // 10000
    const int E  = in_sizes[2] / 128;   // 40000

    float *p_skip, *p_h, *p_u1, *p_u2, *p_sph;
    cudaGetSymbolAddress((void**)&p_skip, g_skip);
    cudaGetSymbolAddress((void**)&p_h,    g_h);
    cudaGetSymbolAddress((void**)&p_u1,   g_u1);
    cudaGetSymbolAddress((void**)&p_u2,   g_u2);
    cudaGetSymbolAddress((void**)&p_sph,  g_sph);

    const int SMEM_MSG = 102400;  // 25600 floats
    cudaFuncSetAttribute((const void*)msg1_kernel,
                         cudaFuncAttributeMaxDynamicSharedMemorySize, SMEM_MSG);
    cudaFuncSetAttribute((const void*)msg2_kernel,
                         cudaFuncAttributeMaxDynamicSharedMemorySize, SMEM_MSG);

    // sph harmonics + zero scatter buffers
    sh_kernel<<<(E + 255) / 256, 256>>>(edge_vec, E);
    zero_kernel<<<256, 256>>>(Nn);

    // node-side GEMMs
    gemm_kernel<0, 0><<<dim3(4, (Nn + 63) / 64), 256>>>(
        node_feature, w_skip, b_skip, nullptr, p_skip, Nn, 256, 256);
    gemm_kernel<0, 0><<<dim3(1, (Nn + 63) / 64), 256>>>(
        node_feature, w_node, b_node, nullptr, p_h, Nn, 64, 256);

    // edge MLP first layers (with softplus)
    gemm_kernel<1, 0><<<dim3(2, (E + 63) / 64), 256>>>(
        edge_feature, fc1_w1, fc1_b1, nullptr, p_u1, E, 128, 128);
    gemm_kernel<1, 0><<<dim3(2, (E + 63) / 64), 256>>>(
        edge_feature, fc2_w1, fc2_b1, nullptr, p_u2, E, 128, 128);

    const int nblk = (E + 63) / 64;
    msg1_kernel<<<nblk, 256, SMEM_MSG>>>(edge_index, fc1_w2, fc1_b2, E);
    h1_finalize_kernel<<<256, 256>>>(Nn);
    msg2_kernel<<<nblk, 256, SMEM_MSG>>>(edge_index, fc2_w2, fc2_b2, E);
    h2_finalize_kernel<<<256, 256>>>(Nn);

    bn_stats_kernel<<<64, 256>>>(Nn);
    bn_apply_kernel<<<256, 256>>>(bn_gamma, bn_beta, Nn);

    // out = softplus(sph @ w_out + b_out) + skip
    gemm_kernel<1, 1><<<dim3(4, (Nn + 63) / 64), 256>>>(
        p_sph, w_out, b_out, p_skip, out, Nn, 256, 64);
}

// round 4
// speedup vs baseline: 1.2776x; 1.2776x over previous
#include <cuda_runtime.h>
#include <math.h>
#include <stdint.h>

// Problem constants: N=10000, E=40000, IN_CH=256, OUT_CH=256,
// EDGE_DIM=128, NS=64, NV=8, WN1=WN2=5120.

#define MAXN 10000
#define MAXE 40000

// ---------------- scratch (static __device__ — no allocations allowed) -----
__device__ float g_skip[MAXN * 256];
__device__ float g_h   [MAXN * 64];
__device__ float g_u1  [MAXE * 128];
__device__ float g_u2  [MAXE * 128];
__device__ float g_shb [MAXE * 8];     // sh1 (3) + sh2 (5)
__device__ float g_h1  [MAXN * 128];
__device__ float g_cnt [MAXN];
__device__ float g_h2  [MAXN * 64];
__device__ float g_mu  [64];
__device__ float g_var [64];
__device__ float g_sph [MAXN * 64];
__device__ float g_w1t [5120 * 128];   // fc1_w2 transposed [5120,128]
__device__ float g_w2t [5120 * 128];   // fc2_w2 transposed

__device__ __forceinline__ float softplusf(float x) {
    return fmaxf(x, 0.0f) + log1pf(expf(-fabsf(x)));
}
__device__ __forceinline__ uint32_t f2tf32(float f) {
    uint32_t r;
    asm("cvt.rna.tf32.f32 %0, %1;" : "=r"(r) : "f"(f));
    return r;
}
__device__ __forceinline__ void mma_m16n8k8(float c[4],
    uint32_t a0, uint32_t a1, uint32_t a2, uint32_t a3,
    uint32_t b0, uint32_t b1)
{
    asm volatile(
        "mma.sync.aligned.m16n8k8.row.col.f32.tf32.tf32.f32 "
        "{%0,%1,%2,%3}, {%4,%5,%6,%7}, {%8,%9}, {%0,%1,%2,%3};"
        : "+f"(c[0]), "+f"(c[1]), "+f"(c[2]), "+f"(c[3])
        : "r"(a0), "r"(a1), "r"(a2), "r"(a3), "r"(b0), "r"(b1));
}

// ======================= generic fp32 GEMM (small mats) =====================
template <int ACT, int ADD>
__global__ void __launch_bounds__(256) gemm_kernel(
    const float* __restrict__ A, const float* __restrict__ B,
    const float* __restrict__ bias, const float* __restrict__ addsrc,
    float* __restrict__ C, int M, int N, int K)
{
    __shared__ float As[16][64];
    __shared__ float Bs[16][64];
    const int bm = blockIdx.y * 64, bn = blockIdx.x * 64;
    const int tid = threadIdx.x;
    const int ty = tid >> 4, tx = tid & 15;

    float acc[4][4] = {};
    for (int k0 = 0; k0 < K; k0 += 16) {
#pragma unroll
        for (int l = 0; l < 4; ++l) {
            int idx = tid + l * 256;
            int r = idx >> 4, c = idx & 15;
            int gr = bm + r;
            As[c][r] = (gr < M) ? A[(size_t)gr * K + k0 + c] : 0.0f;
        }
#pragma unroll
        for (int l = 0; l < 4; ++l) {
            int idx = tid + l * 256;
            int r = idx >> 6, c = idx & 63;
            Bs[r][c] = B[(size_t)(k0 + r) * N + bn + c];
        }
        __syncthreads();
#pragma unroll
        for (int kk = 0; kk < 16; ++kk) {
            float ra[4], rb[4];
#pragma unroll
            for (int a = 0; a < 4; ++a) ra[a] = As[kk][ty * 4 + a];
#pragma unroll
            for (int b = 0; b < 4; ++b) rb[b] = Bs[kk][tx * 4 + b];
#pragma unroll
            for (int a = 0; a < 4; ++a)
#pragma unroll
                for (int b = 0; b < 4; ++b)
                    acc[a][b] = fmaf(ra[a], rb[b], acc[a][b]);
        }
        __syncthreads();
    }
#pragma unroll
    for (int a = 0; a < 4; ++a) {
        int m = bm + ty * 4 + a;
        if (m >= M) continue;
#pragma unroll
        for (int b = 0; b < 4; ++b) {
            int n = bn + tx * 4 + b;
            float v = acc[a][b] + bias[n];
            if (ACT) v = softplusf(v);
            if (ADD) v += addsrc[(size_t)m * N + n];
            C[(size_t)m * N + n] = v;
        }
    }
}

// ---------------- weight transpose [128,5120] -> [5120,128] -----------------
__global__ void transpose_kernel(const float* __restrict__ W, float* __restrict__ WT)
{
    __shared__ float t[32][33];
    const int j0 = blockIdx.x * 32, d0 = blockIdx.y * 32;
    for (int r = threadIdx.y; r < 32; r += 8)
        t[r][threadIdx.x] = W[(size_t)(d0 + r) * 5120 + j0 + threadIdx.x];
    __syncthreads();
    for (int r = threadIdx.y; r < 32; r += 8)
        WT[(size_t)(j0 + r) * 128 + d0 + threadIdx.x] = t[threadIdx.x][r];
}

// ---------------- spherical harmonics per edge -----------------------------
__global__ void sh_kernel(const float* __restrict__ ev, int E)
{
    int e = blockIdx.x * blockDim.x + threadIdx.x;
    if (e >= E) return;
    float x = ev[e * 3 + 0], y = ev[e * 3 + 1], z = ev[e * 3 + 2];
    float rn = rsqrtf(x * x + y * y + z * z);
    x *= rn; y *= rn; z *= rn;
    const float s3 = 1.7320508075688772f;
    const float s5 = 2.2360679774997896f;
    float* o = g_shb + (size_t)e * 8;
    o[0] = s3 * x;
    o[1] = s3 * y;
    o[2] = s3 * z;
    o[3] = s5 * s3 * x * z;
    o[4] = s5 * s3 * x * y;
    o[5] = s5 * (y * y - 0.5f * (x * x + z * z));
    o[6] = s5 * s3 * y * z;
    o[7] = s5 * (s3 * 0.5f) * (z * z - x * x);
}

__global__ void zero_kernel(int Nn)
{
    int t = blockIdx.x * blockDim.x + threadIdx.x;
    int gs = gridDim.x * blockDim.x;
    for (int i = t; i < Nn * 128; i += gs) g_h1[i] = 0.0f;
    for (int i = t; i < Nn * 64;  i += gs) g_h2[i] = 0.0f;
    for (int i = t; i < Nn;       i += gs) g_cnt[i] = 0.0f;
}

// ======================= mma.sync fused message pass =========================
// Per block: 128 edges, 8 warps. For each of 80 column-chunks:
//   P[128,64] = [U|1](tf32)[128x136] @ [Wchunk|bias]^T(tf32)[64x136]
// computed with m16n8k8 tf32 MMAs (warp w owns rows 16w..16w+15), then folded
// into per-edge accumulators by the S contraction; atomically scattered.
//
// smem (floats): sU [128][140] @0, sW0 [64][140] @17920, sW1 @26880,
//                sS [128][81] @35840.  Total 46208 floats = 184832 B.
#define SU_STRIDE 140
#define SMEM_MSG_B 184832

__device__ __forceinline__ void fill_W(float* __restrict__ sW,
    const float* __restrict__ WT, const float* __restrict__ B2,
    int ch, int tid)
{
    for (int slot = tid; slot < 64 * 35; slot += 256) {
        int row = slot / 35;
        int c4  = slot - row * 35;
        uint4 v = make_uint4(0u, 0u, 0u, 0u);
        int g = ch * 64 + row;
        if (c4 < 32) {
            const float4 w = *reinterpret_cast<const float4*>(
                WT + (size_t)g * 128 + c4 * 4);
            v.x = f2tf32(w.x); v.y = f2tf32(w.y);
            v.z = f2tf32(w.z); v.w = f2tf32(w.w);
        } else if (c4 == 32) {
            v.x = f2tf32(B2[g]);
        }
        *reinterpret_cast<uint4*>(sW + row * SU_STRIDE + c4 * 4) = v;
    }
}

template <int PASS>
__global__ void __launch_bounds__(256, 1) msg_mma_kernel(
    const int* __restrict__ ei, const float* __restrict__ U,
    const float* __restrict__ WT, const float* __restrict__ B2, int E)
{
    extern __shared__ __align__(16) float smem[];
    float* sU  = smem;                    // [128][140]
    float* sW0 = smem + 17920;            // [64][140]
    float* sW1 = smem + 26880;
    float* sS  = smem + 35840;            // [128][81]

    const int tid = threadIdx.x;
    const int wid = tid >> 5, lane = tid & 31;
    const int e0 = blockIdx.x * 128;
    const int ne = min(128, E - e0);

    // ---- fill A tile: [U | 1 | 0] as tf32 ----
    for (int slot = tid; slot < 128 * 35; slot += 256) {
        int row = slot / 35;
        int c4  = slot - row * 35;
        uint4 v = make_uint4(0u, 0u, 0u, 0u);
        if (row < ne) {
            if (c4 < 32) {
                const float4 u = *reinterpret_cast<const float4*>(
                    U + (size_t)(e0 + row) * 128 + c4 * 4);
                v.x = f2tf32(u.x); v.y = f2tf32(u.y);
                v.z = f2tf32(u.z); v.w = f2tf32(u.w);
            } else if (c4 == 32) {
                v.x = f2tf32(1.0f);
            }
        }
        *reinterpret_cast<uint4*>(sU + row * SU_STRIDE + c4 * 4) = v;
    }

    // ---- fill S tile ----
    if (PASS == 1) {
        for (int idx = tid; idx < 128 * 64; idx += 256) {
            int e = idx >> 6, i = idx & 63;
            float v = 0.0f;
            if (e < ne) {
                int dst = ei[E + e0 + e];
                v = g_h[(size_t)dst * 64 + i];
            }
            sS[e * 81 + i] = v;
        }
    } else {
        for (int idx = tid; idx < 128 * 80; idx += 256) {
            int e = idx / 80, j = idx - e * 80;
            float v = 0.0f;
            if (e < ne) {
                int dst = ei[E + e0 + e];
                const float* he = g_h1 + (size_t)dst * 128;
                if (j < 64) {
                    v = he[j];
                } else if (j < 72) {
                    int i = j - 64; float p = 0.0f;
#pragma unroll
                    for (int m = 0; m < 3; ++m)
                        p += he[64 + i * 3 + m] * g_shb[(size_t)(e0 + e) * 8 + m];
                    v = p * 0.5773502691896258f;
                } else {
                    int i = j - 72; float p = 0.0f;
#pragma unroll
                    for (int m = 0; m < 5; ++m)
                        p += he[88 + i * 5 + m] * g_shb[(size_t)(e0 + e) * 8 + 3 + m];
                    v = p * 0.4472135954999579f;
                }
            }
            sS[e * 81 + j] = v;
        }
    }

    fill_W(sW0, WT, B2, 0, tid);
    __syncthreads();

    const int r0 = wid * 16 + (lane >> 2);
    const int r1 = r0 + 8;
    const int qlo = (lane & 3) * 2;
    const uint32_t* U32 = reinterpret_cast<const uint32_t*>(sU);

    float acc0[2][16];
    float acc1[2][2], acc2[2][2];
#pragma unroll
    for (int e = 0; e < 2; ++e) {
#pragma unroll
        for (int c = 0; c < 16; ++c) acc0[e][c] = 0.0f;
        acc1[e][0] = acc1[e][1] = 0.0f;
        acc2[e][0] = acc2[e][1] = 0.0f;
    }

    for (int ch = 0; ch < 80; ++ch) {
        if (ch + 1 < 80)
            fill_W(((ch + 1) & 1) ? sW1 : sW0, WT, B2, ch + 1, tid);

        const uint32_t* W32 = reinterpret_cast<const uint32_t*>(
            (ch & 1) ? sW1 : sW0);

        float c[8][4];
#pragma unroll
        for (int nt = 0; nt < 8; ++nt)
            c[nt][0] = c[nt][1] = c[nt][2] = c[nt][3] = 0.0f;

        const int la = lane & 3;
        const int qb = (lane >> 2) * SU_STRIDE;
#pragma unroll 4
        for (int ks = 0; ks < 17; ++ks) {
            int k0 = ks * 8 + la;
            uint32_t a0 = U32[r0 * SU_STRIDE + k0];
            uint32_t a1 = U32[r1 * SU_STRIDE + k0];
            uint32_t a2 = U32[r0 * SU_STRIDE + k0 + 4];
            uint32_t a3 = U32[r1 * SU_STRIDE + k0 + 4];
#pragma unroll
            for (int nt = 0; nt < 8; ++nt) {
                uint32_t b0 = W32[nt * 8 * SU_STRIDE + qb + k0];
                uint32_t b1 = W32[nt * 8 * SU_STRIDE + qb + k0 + 4];
                mma_m16n8k8(c[nt], a0, a1, a2, a3, b0, b1);
            }
        }

        if (PASS == 2 || ch < 64) {
            float s0 = sS[r0 * 81 + ch];
            float s1 = sS[r1 * 81 + ch];
#pragma unroll
            for (int nt = 0; nt < 8; ++nt) {
                acc0[0][2 * nt]     = fmaf(s0, c[nt][0], acc0[0][2 * nt]);
                acc0[0][2 * nt + 1] = fmaf(s0, c[nt][1], acc0[0][2 * nt + 1]);
                acc0[1][2 * nt]     = fmaf(s1, c[nt][2], acc0[1][2 * nt]);
                acc0[1][2 * nt + 1] = fmaf(s1, c[nt][3], acc0[1][2 * nt + 1]);
            }
        } else if (ch < 72) {
            const int ib = (ch - 64) * 8;
#pragma unroll
            for (int nt = 0; nt < 8; ++nt) {
                float s0 = sS[r0 * 81 + ib + nt];
                float s1 = sS[r1 * 81 + ib + nt];
                acc1[0][0] = fmaf(s0, c[nt][0], acc1[0][0]);
                acc1[0][1] = fmaf(s0, c[nt][1], acc1[0][1]);
                acc1[1][0] = fmaf(s1, c[nt][2], acc1[1][0]);
                acc1[1][1] = fmaf(s1, c[nt][3], acc1[1][1]);
            }
        } else {
            const int ib = (ch - 72) * 8;
#pragma unroll
            for (int nt = 0; nt < 8; ++nt) {
                float s0 = sS[r0 * 81 + ib + nt];
                float s1 = sS[r1 * 81 + ib + nt];
                acc2[0][0] = fmaf(s0, c[nt][0], acc2[0][0]);
                acc2[0][1] = fmaf(s0, c[nt][1], acc2[0][1]);
                acc2[1][0] = fmaf(s1, c[nt][2], acc2[1][0]);
                acc2[1][1] = fmaf(s1, c[nt][3], acc2[1][1]);
            }
        }
        __syncthreads();
    }

    // ---- epilogue scatter ----
#pragma unroll
    for (int e = 0; e < 2; ++e) {
        int r = e ? r1 : r0;
        if (r >= ne) continue;
        int src = ei[e0 + r];
        if (PASS == 1) {
            const float C1 = 0.125f;
            float* d1 = g_h1 + (size_t)src * 128;
#pragma unroll
            for (int nt = 0; nt < 8; ++nt) {
                atomicAdd(d1 + nt * 8 + qlo,     C1 * acc0[e][2 * nt]);
                atomicAdd(d1 + nt * 8 + qlo + 1, C1 * acc0[e][2 * nt + 1]);
            }
            float sh[8];
#pragma unroll
            for (int m = 0; m < 8; ++m) sh[m] = g_shb[(size_t)(e0 + r) * 8 + m];
#pragma unroll
            for (int b = 0; b < 2; ++b) {
                int kk = qlo + b;
                float a1v = C1 * acc1[e][b];
                float a2v = C1 * acc2[e][b];
#pragma unroll
                for (int m = 0; m < 3; ++m)
                    atomicAdd(d1 + 64 + kk * 3 + m, a1v * sh[m]);
#pragma unroll
                for (int m = 0; m < 5; ++m)
                    atomicAdd(d1 + 88 + kk * 5 + m, a2v * sh[3 + m]);
            }
            if ((lane & 3) == 0) atomicAdd(&g_cnt[src], 1.0f);
        } else {
            const float INV = 0.11180339887498948f;  // 1/sqrt(80)
            float* d2 = g_h2 + (size_t)src * 64;
#pragma unroll
            for (int nt = 0; nt < 8; ++nt) {
                atomicAdd(d2 + nt * 8 + qlo,     INV * acc0[e][2 * nt]);
                atomicAdd(d2 + nt * 8 + qlo + 1, INV * acc0[e][2 * nt + 1]);
            }
        }
    }
}

// ---------------- finalize / BN / epilogue ----------------------------------
__global__ void h1_finalize_kernel(int Nn)
{
    int t = blockIdx.x * blockDim.x + threadIdx.x;
    int gs = gridDim.x * blockDim.x;
    for (int idx = t; idx < Nn * 128; idx += gs) {
        int n = idx >> 7, c = idx & 127;
        float cnt = fmaxf(g_cnt[n], 1.0f);
        float v = g_h1[idx] / cnt;
        if (c < 64) v += g_h[n * 64 + c];
        g_h1[idx] = v;
    }
}

__global__ void h2_finalize_kernel(int Nn)
{
    int t = blockIdx.x * blockDim.x + threadIdx.x;
    int gs = gridDim.x * blockDim.x;
    for (int idx = t; idx < Nn * 64; idx += gs) {
        int n = idx >> 6;
        g_h2[idx] /= fmaxf(g_cnt[n], 1.0f);
    }
}

__global__ void bn_stats_kernel(int Nn)
{
    __shared__ float rs[256], rs2[256];
    const int c = blockIdx.x;
    float s = 0.0f, s2 = 0.0f;
    for (int n = threadIdx.x; n < Nn; n += 256) {
        float x = g_h2[(size_t)n * 64 + c];
        s += x; s2 += x * x;
    }
    rs[threadIdx.x] = s; rs2[threadIdx.x] = s2;
    __syncthreads();
    for (int off = 128; off > 0; off >>= 1) {
        if (threadIdx.x < off) {
            rs[threadIdx.x]  += rs[threadIdx.x + off];
            rs2[threadIdx.x] += rs2[threadIdx.x + off];
        }
        __syncthreads();
    }
    if (threadIdx.x == 0) {
        float mu = rs[0] / (float)Nn;
        g_mu[c]  = mu;
        g_var[c] = rs2[0] / (float)Nn - mu * mu;
    }
}

__global__ void bn_apply_kernel(const float* __restrict__ gamma,
                                const float* __restrict__ beta, int Nn)
{
    int t = blockIdx.x * blockDim.x + threadIdx.x;
    int gs = gridDim.x * blockDim.x;
    for (int idx = t; idx < Nn * 64; idx += gs) {
        int c = idx & 63;
        float x = (g_h2[idx] - g_mu[c]) * rsqrtf(g_var[c] + 1e-5f) * gamma[c] + beta[c];
        g_sph[idx] = softplusf(x);
    }
}

// ---------------- launch ----------------------------------------------------
extern "C" void kernel_launch(void* const* d_in, const int* in_sizes, int n_in,
                              void* d_out, int out_size)
{
    const float* node_feature = (const float*)d_in[0];
    const int*   edge_index   = (const int*)d_in[1];
    const float* edge_feature = (const float*)d_in[2];
    const float* edge_vec     = (const float*)d_in[3];
    const float* w_node = (const float*)d_in[4];
    const float* b_node = (const float*)d_in[5];
    const float* w_skip = (const float*)d_in[6];
    const float* b_skip = (const float*)d_in[7];
    const float* fc1_w1 = (const float*)d_in[8];
    const float* fc1_b1 = (const float*)d_in[9];
    const float* fc1_w2 = (const float*)d_in[10];
    const float* fc1_b2 = (const float*)d_in[11];
    const float* fc2_w1 = (const float*)d_in[12];
    const float* fc2_b1 = (const float*)d_in[13];
    const float* fc2_w2 = (const float*)d_in[14];
    const float* fc2_b2 = (const float*)d_in[15];
    const float* bn_gamma = (const float*)d_in[16];
    const float* bn_beta  = (const float*)d_in[17];
    const float* w_out = (const float*)d_in[18];
    const float* b_out = (const float*)d_in[19];
    float* out = (float*)d_out;

    const int Nn = in_sizes[0] / 256;   // 10000
    const int E  = in_sizes[2] / 128;   // 40000

    float *p_skip, *p_h, *p_u1, *p_u2, *p_sph, *p_w1t, *p_w2t;
    cudaGetSymbolAddress((void**)&p_skip, g_skip);
    cudaGetSymbolAddress((void**)&p_h,    g_h);
    cudaGetSymbolAddress((void**)&p_u1,   g_u1);
    cudaGetSymbolAddress((void**)&p_u2,   g_u2);
    cudaGetSymbolAddress((void**)&p_sph,  g_sph);
    cudaGetSymbolAddress((void**)&p_w1t,  g_w1t);
    cudaGetSymbolAddress((void**)&p_w2t,  g_w2t);

    cudaFuncSetAttribute((const void*)msg_mma_kernel<1>,
                         cudaFuncAttributeMaxDynamicSharedMemorySize, SMEM_MSG_B);
    cudaFuncSetAttribute((const void*)msg_mma_kernel<2>,
                         cudaFuncAttributeMaxDynamicSharedMemorySize, SMEM_MSG_B);

    // weight transposes + sph harmonics + zero scatter buffers
    transpose_kernel<<<dim3(160, 4), dim3(32, 8)>>>(fc1_w2, p_w1t);
    transpose_kernel<<<dim3(160, 4), dim3(32, 8)>>>(fc2_w2, p_w2t);
    sh_kernel<<<(E + 255) / 256, 256>>>(edge_vec, E);
    zero_kernel<<<256, 256>>>(Nn);

    // node-side GEMMs
    gemm_kernel<0, 0><<<dim3(4, (Nn + 63) / 64), 256>>>(
        node_feature, w_skip, b_skip, nullptr, p_skip, Nn, 256, 256);
    gemm_kernel<0, 0><<<dim3(1, (Nn + 63) / 64), 256>>>(
        node_feature, w_node, b_node, nullptr, p_h, Nn, 64, 256);

    // edge MLP first layers (with softplus)
    gemm_kernel<1, 0><<<dim3(2, (E + 63) / 64), 256>>>(
        edge_feature, fc1_w1, fc1_b1, nullptr, p_u1, E, 128, 128);
    gemm_kernel<1, 0><<<dim3(2, (E + 63) / 64), 256>>>(
        edge_feature, fc2_w1, fc2_b1, nullptr, p_u2, E, 128, 128);

    const int nblk = (E + 127) / 128;
    msg_mma_kernel<1><<<nblk, 256, SMEM_MSG_B>>>(edge_index, p_u1, p_w1t, fc1_b2, E);
    h1_finalize_kernel<<<256, 256>>>(Nn);
    msg_mma_kernel<2><<<nblk, 256, SMEM_MSG_B>>>(edge_index, p_u2, p_w2t, fc2_b2, E);
    h2_finalize_kernel<<<256, 256>>>(Nn);

    bn_stats_kernel<<<64, 256>>>(Nn);
    bn_apply_kernel<<<256, 256>>>(bn_gamma, bn_beta, Nn);

    // out = softplus(sph @ w_out + b_out) + skip
    gemm_kernel<1, 1><<<dim3(4, (Nn + 63) / 64), 256>>>(
        p_sph, w_out, b_out, p_skip, out, Nn, 256, 64);
}

// round 5
// speedup vs baseline: 1.6351x; 1.2798x over previous
#include <cuda_runtime.h>
#include <math.h>
#include <stdint.h>

// Problem constants: N=10000, E=40000, IN_CH=256, OUT_CH=256,
// EDGE_DIM=128, NS=64, NV=8, WN1=WN2=5120.

#define MAXN 10000
#define MAXE 40000

// ---------------- scratch (static __device__ — no allocations allowed) -----
__device__ float g_skip[MAXN * 256];
__device__ float g_h   [MAXN * 64];
__device__ float g_u1  [MAXE * 128];
__device__ float g_u2  [MAXE * 128];
__device__ float g_shb [MAXE * 8];     // sh1 (3) + sh2 (5)
__device__ float g_h1  [MAXN * 128];
__device__ float g_cnt [MAXN];
__device__ float g_h2  [MAXN * 64];
__device__ float g_mu  [64];
__device__ float g_var [64];
__device__ float g_sph [MAXN * 64];
__device__ float g_w1t [5120 * 128];   // fc1_w2 transposed [5120,128], tf32-rounded
__device__ float g_w2t [5120 * 128];   // fc2_w2 transposed, tf32-rounded

__device__ __forceinline__ float softplusf(float x) {
    return fmaxf(x, 0.0f) + log1pf(expf(-fabsf(x)));
}
__device__ __forceinline__ uint32_t f2tf32(float f) {
    uint32_t r;
    asm("cvt.rna.tf32.f32 %0, %1;" : "=r"(r) : "f"(f));
    return r;
}
__device__ __forceinline__ uint32_t smem_u32(const void* p) {
    uint32_t a;
    asm("{ .reg .u64 t; cvta.to.shared.u64 t, %1; cvt.u32.u64 %0, t; }"
        : "=r"(a) : "l"(p));
    return a;
}
__device__ __forceinline__ void mma_m16n8k8(float c[4],
    uint32_t a0, uint32_t a1, uint32_t a2, uint32_t a3,
    uint32_t b0, uint32_t b1)
{
    asm volatile(
        "mma.sync.aligned.m16n8k8.row.col.f32.tf32.tf32.f32 "
        "{%0,%1,%2,%3}, {%4,%5,%6,%7}, {%8,%9}, {%0,%1,%2,%3};"
        : "+f"(c[0]), "+f"(c[1]), "+f"(c[2]), "+f"(c[3])
        : "r"(a0), "r"(a1), "r"(a2), "r"(a3), "r"(b0), "r"(b1));
}
#define CP_ASYNC16(dst, src) \
    asm volatile("cp.async.cg.shared.global [%0], [%1], 16;" :: "r"(dst), "l"(src))
#define CP_COMMIT()  asm volatile("cp.async.commit_group;" ::: "memory")
#define CP_WAIT0()   asm volatile("cp.async.wait_group 0;" ::: "memory")

// ======================= generic fp32 GEMM (small mats) =====================
template <int ACT, int ADD>
__global__ void __launch_bounds__(256) gemm_kernel(
    const float* __restrict__ A, const float* __restrict__ B,
    const float* __restrict__ bias, const float* __restrict__ addsrc,
    float* __restrict__ C, int M, int N, int K)
{
    __shared__ float As[16][64];
    __shared__ float Bs[16][64];
    const int bm = blockIdx.y * 64, bn = blockIdx.x * 64;
    const int tid = threadIdx.x;
    const int ty = tid >> 4, tx = tid & 15;

    float acc[4][4] = {};
    for (int k0 = 0; k0 < K; k0 += 16) {
#pragma unroll
        for (int l = 0; l < 4; ++l) {
            int idx = tid + l * 256;
            int r = idx >> 4, c = idx & 15;
            int gr = bm + r;
            As[c][r] = (gr < M) ? A[(size_t)gr * K + k0 + c] : 0.0f;
        }
#pragma unroll
        for (int l = 0; l < 4; ++l) {
            int idx = tid + l * 256;
            int r = idx >> 6, c = idx & 63;
            Bs[r][c] = B[(size_t)(k0 + r) * N + bn + c];
        }
        __syncthreads();
#pragma unroll
        for (int kk = 0; kk < 16; ++kk) {
            float ra[4], rb[4];
#pragma unroll
            for (int a = 0; a < 4; ++a) ra[a] = As[kk][ty * 4 + a];
#pragma unroll
            for (int b = 0; b < 4; ++b) rb[b] = Bs[kk][tx * 4 + b];
#pragma unroll
            for (int a = 0; a < 4; ++a)
#pragma unroll
                for (int b = 0; b < 4; ++b)
                    acc[a][b] = fmaf(ra[a], rb[b], acc[a][b]);
        }
        __syncthreads();
    }
#pragma unroll
    for (int a = 0; a < 4; ++a) {
        int m = bm + ty * 4 + a;
        if (m >= M) continue;
#pragma unroll
        for (int b = 0; b < 4; ++b) {
            int n = bn + tx * 4 + b;
            float v = acc[a][b] + bias[n];
            if (ACT) v = softplusf(v);
            if (ADD) v += addsrc[(size_t)m * N + n];
            C[(size_t)m * N + n] = v;
        }
    }
}

// ---- weight transpose [128,5120] -> [5120,128], rounded to tf32 ----------
__global__ void transpose_kernel(const float* __restrict__ W, float* __restrict__ WT)
{
    __shared__ float t[32][33];
    const int j0 = blockIdx.x * 32, d0 = blockIdx.y * 32;
    for (int r = threadIdx.y; r < 32; r += 8)
        t[r][threadIdx.x] = W[(size_t)(d0 + r) * 5120 + j0 + threadIdx.x];
    __syncthreads();
    for (int r = threadIdx.y; r < 32; r += 8)
        WT[(size_t)(j0 + r) * 128 + d0 + threadIdx.x] =
            __uint_as_float(f2tf32(t[threadIdx.x][r]));
}

// ---------------- spherical harmonics per edge -----------------------------
__global__ void sh_kernel(const float* __restrict__ ev, int E)
{
    int e = blockIdx.x * blockDim.x + threadIdx.x;
    if (e >= E) return;
    float x = ev[e * 3 + 0], y = ev[e * 3 + 1], z = ev[e * 3 + 2];
    float rn = rsqrtf(x * x + y * y + z * z);
    x *= rn; y *= rn; z *= rn;
    const float s3 = 1.7320508075688772f;
    const float s5 = 2.2360679774997896f;
    float* o = g_shb + (size_t)e * 8;
    o[0] = s3 * x;
    o[1] = s3 * y;
    o[2] = s3 * z;
    o[3] = s5 * s3 * x * z;
    o[4] = s5 * s3 * x * y;
    o[5] = s5 * (y * y - 0.5f * (x * x + z * z));
    o[6] = s5 * s3 * y * z;
    o[7] = s5 * (s3 * 0.5f) * (z * z - x * x);
}

__global__ void zero_kernel(int Nn)
{
    int t = blockIdx.x * blockDim.x + threadIdx.x;
    int gs = gridDim.x * blockDim.x;
    for (int i = t; i < Nn * 128; i += gs) g_h1[i] = 0.0f;
    for (int i = t; i < Nn * 64;  i += gs) g_h2[i] = 0.0f;
    for (int i = t; i < Nn;       i += gs) g_cnt[i] = 0.0f;
}

// ======================= mma.sync fused message pass =========================
// 128 edges/CTA, 512 threads, 16 warps: warp = (mtile = wid>>1, nhalf = wid&1).
// Per chunk ch (80): P[128,64] = U[128,128]@Wch[64,128]^T + bias via tf32 MMA
// (A in registers, W cp.async-staged in fragment-permuted smem), folded into
// per-edge accumulators by the S contraction, then atomically scattered.
//
// smem (floats): sW0[8448] sW1[8448] sS[128*81] sBias[5120] = 32384 fl.
#define SMEM_MSG_F 32384
#define SMEM_MSG_B (SMEM_MSG_F * 4)

// W smem layout: row (np*16+ks) of 132 words; within row:
//   word = lq*16 + ((comp + (lq>>1))&3)*4 + la
// where element B[k = ks*8 + la + 4*b01, n = nt*8 + lq], np = nt>>1,
// comp = (nt&1)*2 + b01.
__device__ __forceinline__ void fill_W_async(float* __restrict__ sW,
    const float* __restrict__ WT, int ch, int tid)
{
#pragma unroll
    for (int i = 0; i < 4; ++i) {
        int idx = tid + i * 512;
        int n  = (idx >> 3) & 63;
        int kb = i * 8 + (idx & 7);
        const float* src = WT + (size_t)(ch * 64 + n) * 128 + kb * 4;
        int nt = n >> 3, np = n >> 4, lq = n & 7, ks = kb >> 1;
        int comp = ((nt & 1) << 1) | (kb & 1);
        int p = (comp + (lq >> 1)) & 3;
        uint32_t dst = smem_u32(sW + (np * 16 + ks) * 132 + lq * 16 + p * 4);
        CP_ASYNC16(dst, src);
    }
}

template <int PASS>
__global__ void __launch_bounds__(512, 1) msg_mma_kernel(
    const int* __restrict__ ei, const float* __restrict__ U,
    const float* __restrict__ WT, const float* __restrict__ B2, int E)
{
    extern __shared__ __align__(16) float smem[];
    float* sW0   = smem;
    float* sW1   = smem + 8448;
    float* sS    = smem + 16896;     // [128][81]
    float* sBias = smem + 27264;     // [5120]

    const int tid = threadIdx.x;
    const int wid = tid >> 5, lane = tid & 31;
    const int mt = wid >> 1, nh = wid & 1;
    const int lq = lane >> 2, la = lane & 3;
    const int e0 = blockIdx.x * 128;
    const int ne = min(128, E - e0);
    const int r0 = mt * 16 + lq, r1 = r0 + 8;
    const bool v0 = r0 < ne, v1 = r1 < ne;

    // kick off W chunk 0 load
    fill_W_async(sW0, WT, 0, tid);
    CP_COMMIT();

    // bias to smem
    for (int i = tid; i < 5120; i += 512) sBias[i] = B2[i];

    // ---- S tile ----
    if (PASS == 1) {
        for (int idx = tid; idx < 128 * 64; idx += 512) {
            int e = idx >> 6, i = idx & 63;
            float v = 0.0f;
            if (e < ne) {
                int dst = ei[E + e0 + e];
                v = g_h[(size_t)dst * 64 + i];
            }
            sS[e * 81 + i] = v;
        }
    } else {
        for (int idx = tid; idx < 128 * 80; idx += 512) {
            int e = idx / 80, j = idx - e * 80;
            float v = 0.0f;
            if (e < ne) {
                int dst = ei[E + e0 + e];
                const float* he = g_h1 + (size_t)dst * 128;
                if (j < 64) {
                    v = he[j];
                } else if (j < 72) {
                    int i = j - 64; float p = 0.0f;
#pragma unroll
                    for (int m = 0; m < 3; ++m)
                        p += he[64 + i * 3 + m] * g_shb[(size_t)(e0 + e) * 8 + m];
                    v = p * 0.5773502691896258f;
                } else {
                    int i = j - 72; float p = 0.0f;
#pragma unroll
                    for (int m = 0; m < 5; ++m)
                        p += he[88 + i * 5 + m] * g_shb[(size_t)(e0 + e) * 8 + 3 + m];
                    v = p * 0.4472135954999579f;
                }
            }
            sS[e * 81 + j] = v;
        }
    }

    // ---- A registers (U rows r0, r1; safe-clamped pointers) ----
    uint32_t A0[16], A1[16], A2[16], A3[16];
    {
        const float* u0 = U + (size_t)(e0 + (v0 ? r0 : 0)) * 128 + la;
        const float* u1 = U + (size_t)(e0 + (v1 ? r1 : 0)) * 128 + la;
#pragma unroll
        for (int ks = 0; ks < 16; ++ks) {
            A0[ks] = v0 ? f2tf32(u0[ks * 8])     : 0u;
            A2[ks] = v0 ? f2tf32(u0[ks * 8 + 4]) : 0u;
            A1[ks] = v1 ? f2tf32(u1[ks * 8])     : 0u;
            A3[ks] = v1 ? f2tf32(u1[ks * 8 + 4]) : 0u;
        }
    }

    // per-thread fragment offsets within a W row (4 comps, bank-swizzled)
    int offc[4];
#pragma unroll
    for (int c = 0; c < 4; ++c)
        offc[c] = lq * 16 + ((c + (lq >> 1)) & 3) * 4 + la;

    float accA[4][4];   // [ntl][{r0c0,r0c1,r1c0,r1c1}]
    float accB[4], accC[4];
#pragma unroll
    for (int i = 0; i < 4; ++i) {
#pragma unroll
        for (int j = 0; j < 4; ++j) accA[i][j] = 0.0f;
        accB[i] = 0.0f; accC[i] = 0.0f;
    }

    CP_WAIT0();
    __syncthreads();

    for (int ch = 0; ch < 80; ++ch) {
        const float* wbuf = (ch & 1) ? sW1 : sW0;
        if (ch + 1 < 80) {
            fill_W_async((ch & 1) ? sW0 : sW1, WT, ch + 1, tid);
            CP_COMMIT();
        }

        // init c from bias
        float c[4][4];
#pragma unroll
        for (int ntl = 0; ntl < 4; ++ntl) {
            const float2 bb = *reinterpret_cast<const float2*>(
                sBias + ch * 64 + (nh * 4 + ntl) * 8 + la * 2);
            c[ntl][0] = bb.x; c[ntl][1] = bb.y;
            c[ntl][2] = bb.x; c[ntl][3] = bb.y;
        }

#pragma unroll
        for (int ks = 0; ks < 16; ++ks) {
#pragma unroll
            for (int ntl = 0; ntl < 4; ++ntl) {
                const int np = nh * 2 + (ntl >> 1);
                const float* row = wbuf + (np * 16 + ks) * 132;
                uint32_t b0 = __float_as_uint(row[offc[(ntl & 1) * 2]]);
                uint32_t b1 = __float_as_uint(row[offc[(ntl & 1) * 2 + 1]]);
                mma_m16n8k8(c[ntl], A0[ks], A1[ks], A2[ks], A3[ks], b0, b1);
            }
        }

        // fold with S
        if (PASS == 2 || ch < 64) {
            float s0 = sS[r0 * 81 + ch];
            float s1 = sS[r1 * 81 + ch];
#pragma unroll
            for (int ntl = 0; ntl < 4; ++ntl) {
                accA[ntl][0] = fmaf(s0, c[ntl][0], accA[ntl][0]);
                accA[ntl][1] = fmaf(s0, c[ntl][1], accA[ntl][1]);
                accA[ntl][2] = fmaf(s1, c[ntl][2], accA[ntl][2]);
                accA[ntl][3] = fmaf(s1, c[ntl][3], accA[ntl][3]);
            }
        } else if (ch < 72) {
#pragma unroll
            for (int ntl = 0; ntl < 4; ++ntl) {
                int i = (ch - 64) * 8 + nh * 4 + ntl;
                float s0 = sS[r0 * 81 + i];
                float s1 = sS[r1 * 81 + i];
                accB[0] = fmaf(s0, c[ntl][0], accB[0]);
                accB[1] = fmaf(s0, c[ntl][1], accB[1]);
                accB[2] = fmaf(s1, c[ntl][2], accB[2]);
                accB[3] = fmaf(s1, c[ntl][3], accB[3]);
            }
        } else {
#pragma unroll
            for (int ntl = 0; ntl < 4; ++ntl) {
                int i = (ch - 72) * 8 + nh * 4 + ntl;
                float s0 = sS[r0 * 81 + i];
                float s1 = sS[r1 * 81 + i];
                accC[0] = fmaf(s0, c[ntl][0], accC[0]);
                accC[1] = fmaf(s0, c[ntl][1], accC[1]);
                accC[2] = fmaf(s1, c[ntl][2], accC[2]);
                accC[3] = fmaf(s1, c[ntl][3], accC[3]);
            }
        }

        if (ch + 1 < 80) CP_WAIT0();
        __syncthreads();
    }

    // ---- epilogue scatter ----
#pragma unroll
    for (int e = 0; e < 2; ++e) {
        int r = e ? r1 : r0;
        if (r >= ne) continue;
        int src = ei[e0 + r];
        if (PASS == 1) {
            const float C1 = 0.125f;
            float* d1 = g_h1 + (size_t)src * 128;
#pragma unroll
            for (int ntl = 0; ntl < 4; ++ntl) {
                int col = (nh * 4 + ntl) * 8 + la * 2;
                atomicAdd(d1 + col,     C1 * accA[ntl][e * 2]);
                atomicAdd(d1 + col + 1, C1 * accA[ntl][e * 2 + 1]);
            }
            float sh[8];
#pragma unroll
            for (int m = 0; m < 8; ++m) sh[m] = g_shb[(size_t)(e0 + r) * 8 + m];
#pragma unroll
            for (int b = 0; b < 2; ++b) {
                int k = la * 2 + b;
                float a1v = C1 * accB[e * 2 + b];
                float a2v = C1 * accC[e * 2 + b];
#pragma unroll
                for (int m = 0; m < 3; ++m)
                    atomicAdd(d1 + 64 + k * 3 + m, a1v * sh[m]);
#pragma unroll
                for (int m = 0; m < 5; ++m)
                    atomicAdd(d1 + 88 + k * 5 + m, a2v * sh[3 + m]);
            }
            if (nh == 0 && la == 0 && e == 0) atomicAdd(&g_cnt[src], 1.0f);
            if (nh == 0 && la == 0 && e == 1) atomicAdd(&g_cnt[src], 1.0f);
        } else {
            const float INV = 0.11180339887498948f;  // 1/sqrt(80)
            float* d2 = g_h2 + (size_t)src * 64;
#pragma unroll
            for (int ntl = 0; ntl < 4; ++ntl) {
                int col = (nh * 4 + ntl) * 8 + la * 2;
                atomicAdd(d2 + col,     INV * accA[ntl][e * 2]);
                atomicAdd(d2 + col + 1, INV * accA[ntl][e * 2 + 1]);
            }
        }
    }
}

// ---------------- finalize / BN / epilogue ----------------------------------
__global__ void h1_finalize_kernel(int Nn)
{
    int t = blockIdx.x * blockDim.x + threadIdx.x;
    int gs = gridDim.x * blockDim.x;
    for (int idx = t; idx < Nn * 128; idx += gs) {
        int n = idx >> 7, c = idx & 127;
        float cnt = fmaxf(g_cnt[n], 1.0f);
        float v = g_h1[idx] / cnt;
        if (c < 64) v += g_h[n * 64 + c];
        g_h1[idx] = v;
    }
}

__global__ void h2_finalize_kernel(int Nn)
{
    int t = blockIdx.x * blockDim.x + threadIdx.x;
    int gs = gridDim.x * blockDim.x;
    for (int idx = t; idx < Nn * 64; idx += gs) {
        int n = idx >> 6;
        g_h2[idx] /= fmaxf(g_cnt[n], 1.0f);
    }
}

__global__ void bn_stats_kernel(int Nn)
{
    __shared__ float rs[256], rs2[256];
    const int c = blockIdx.x;
    float s = 0.0f, s2 = 0.0f;
    for (int n = threadIdx.x; n < Nn; n += 256) {
        float x = g_h2[(size_t)n * 64 + c];
        s += x; s2 += x * x;
    }
    rs[threadIdx.x] = s; rs2[threadIdx.x] = s2;
    __syncthreads();
    for (int off = 128; off > 0; off >>= 1) {
        if (threadIdx.x < off) {
            rs[threadIdx.x]  += rs[threadIdx.x + off];
            rs2[threadIdx.x] += rs2[threadIdx.x + off];
        }
        __syncthreads();
    }
    if (threadIdx.x == 0) {
        float mu = rs[0] / (float)Nn;
        g_mu[c]  = mu;
        g_var[c] = rs2[0] / (float)Nn - mu * mu;
    }
}

__global__ void bn_apply_kernel(const float* __restrict__ gamma,
                                const float* __restrict__ beta, int Nn)
{
    int t = blockIdx.x * blockDim.x + threadIdx.x;
    int gs = gridDim.x * blockDim.x;
    for (int idx = t; idx < Nn * 64; idx += gs) {
        int c = idx & 63;
        float x = (g_h2[idx] - g_mu[c]) * rsqrtf(g_var[c] + 1e-5f) * gamma[c] + beta[c];
        g_sph[idx] = softplusf(x);
    }
}

// ---------------- launch ----------------------------------------------------
extern "C" void kernel_launch(void* const* d_in, const int* in_sizes, int n_in,
                              void* d_out, int out_size)
{
    const float* node_feature = (const float*)d_in[0];
    const int*   edge_index   = (const int*)d_in[1];
    const float* edge_feature = (const float*)d_in[2];
    const float* edge_vec     = (const float*)d_in[3];
    const float* w_node = (const float*)d_in[4];
    const float* b_node = (const float*)d_in[5];
    const float* w_skip = (const float*)d_in[6];
    const float* b_skip = (const float*)d_in[7];
    const float* fc1_w1 = (const float*)d_in[8];
    const float* fc1_b1 = (const float*)d_in[9];
    const float* fc1_w2 = (const float*)d_in[10];
    const float* fc1_b2 = (const float*)d_in[11];
    const float* fc2_w1 = (const float*)d_in[12];
    const float* fc2_b1 = (const float*)d_in[13];
    const float* fc2_w2 = (const float*)d_in[14];
    const float* fc2_b2 = (const float*)d_in[15];
    const float* bn_gamma = (const float*)d_in[16];
    const float* bn_beta  = (const float*)d_in[17];
    const float* w_out = (const float*)d_in[18];
    const float* b_out = (const float*)d_in[19];
    float* out = (float*)d_out;

    const int Nn = in_sizes[0] / 256;   // 10000
    const int E  = in_sizes[2] / 128;   // 40000

    float *p_skip, *p_h, *p_u1, *p_u2, *p_sph, *p_w1t, *p_w2t;
    cudaGetSymbolAddress((void**)&p_skip, g_skip);
    cudaGetSymbolAddress((void**)&p_h,    g_h);
    cudaGetSymbolAddress((void**)&p_u1,   g_u1);
    cudaGetSymbolAddress((void**)&p_u2,   g_u2);
    cudaGetSymbolAddress((void**)&p_sph,  g_sph);
    cudaGetSymbolAddress((void**)&p_w1t,  g_w1t);
    cudaGetSymbolAddress((void**)&p_w2t,  g_w2t);

    cudaFuncSetAttribute((const void*)msg_mma_kernel<1>,
                         cudaFuncAttributeMaxDynamicSharedMemorySize, SMEM_MSG_B);
    cudaFuncSetAttribute((const void*)msg_mma_kernel<2>,
                         cudaFuncAttributeMaxDynamicSharedMemorySize, SMEM_MSG_B);

    // weight transposes (tf32-rounded) + sph harmonics + zero scatter buffers
    transpose_kernel<<<dim3(160, 4), dim3(32, 8)>>>(fc1_w2, p_w1t);
    transpose_kernel<<<dim3(160, 4), dim3(32, 8)>>>(fc2_w2, p_w2t);
    sh_kernel<<<(E + 255) / 256, 256>>>(edge_vec, E);
    zero_kernel<<<256, 256>>>(Nn);

    // node-side GEMMs
    gemm_kernel<0, 0><<<dim3(4, (Nn + 63) / 64), 256>>>(
        node_feature, w_skip, b_skip, nullptr, p_skip, Nn, 256, 256);
    gemm_kernel<0, 0><<<dim3(1, (Nn + 63) / 64), 256>>>(
        node_feature, w_node, b_node, nullptr, p_h, Nn, 64, 256);

    // edge MLP first layers (with softplus)
    gemm_kernel<1, 0><<<dim3(2, (E + 63) / 64), 256>>>(
        edge_feature, fc1_w1, fc1_b1, nullptr, p_u1, E, 128, 128);
    gemm_kernel<1, 0><<<dim3(2, (E + 63) / 64), 256>>>(
        edge_feature, fc2_w1, fc2_b1, nullptr, p_u2, E, 128, 128);

    const int nblk = (E + 127) / 128;
    msg_mma_kernel<1><<<nblk, 512, SMEM_MSG_B>>>(edge_index, p_u1, p_w1t, fc1_b2, E);
    h1_finalize_kernel<<<256, 256>>>(Nn);
    msg_mma_kernel<2><<<nblk, 512, SMEM_MSG_B>>>(edge_index, p_u2, p_w2t, fc2_b2, E);
    h2_finalize_kernel<<<256, 256>>>(Nn);

    bn_stats_kernel<<<64, 256>>>(Nn);
    bn_apply_kernel<<<256, 256>>>(bn_gamma, bn_beta, Nn);

    // out = softplus(sph @ w_out + b_out) + skip
    gemm_kernel<1, 1><<<dim3(4, (Nn + 63) / 64), 256>>>(
        p_sph, w_out, b_out, p_skip, out, Nn, 256, 64);
}

// round 6
// speedup vs baseline: 4.3678x; 2.6712x over previous
#include <cuda_runtime.h>
#include <cuda_fp16.h>
#include <math.h>
#include <stdint.h>

// Problem constants: N=10000, E=40000, IN_CH=256, OUT_CH=256,
// EDGE_DIM=128, NS=64, NV=8, WN1=WN2=5120.

#define MAXN 10000
#define MAXE 40000

// ---------------- scratch (static __device__ — no allocations allowed) -----
__device__ float  g_skip[MAXN * 256];
__device__ float  g_h   [MAXN * 64];
__device__ __half g_u1h [MAXE * 128];
__device__ __half g_u2h [MAXE * 128];
__device__ float  g_shb [MAXE * 8];     // sh1 (3) + sh2 (5)
__device__ float  g_h1  [MAXN * 128];
__device__ float  g_cnt [MAXN];
__device__ float  g_h2  [MAXN * 64];
__device__ float  g_mu  [64];
__device__ float  g_var [64];
__device__ float  g_sph [MAXN * 64];
__device__ __half g_w1t [5120 * 128];   // fc1_w2 transposed [5120,128], fp16
__device__ __half g_w2t [5120 * 128];   // fc2_w2 transposed, fp16

__device__ __forceinline__ float softplusf(float x) {
    return fmaxf(x, 0.0f) + log1pf(expf(-fabsf(x)));
}
__device__ __forceinline__ uint32_t smem_u32(const void* p) {
    uint32_t a;
    asm("{ .reg .u64 t; cvta.to.shared.u64 t, %1; cvt.u32.u64 %0, t; }"
        : "=r"(a) : "l"(p));
    return a;
}
__device__ __forceinline__ void mma_f16_m16n8k16(float c[4],
    uint32_t a0, uint32_t a1, uint32_t a2, uint32_t a3,
    uint32_t b0, uint32_t b1)
{
    asm volatile(
        "mma.sync.aligned.m16n8k16.row.col.f32.f16.f16.f32 "
        "{%0,%1,%2,%3}, {%4,%5,%6,%7}, {%8,%9}, {%0,%1,%2,%3};"
        : "+f"(c[0]), "+f"(c[1]), "+f"(c[2]), "+f"(c[3])
        : "r"(a0), "r"(a1), "r"(a2), "r"(a3), "r"(b0), "r"(b1));
}
#define CP_ASYNC16(dst, src) \
    asm volatile("cp.async.cg.shared.global [%0], [%1], 16;" :: "r"(dst), "l"(src))
#define CP_COMMIT()  asm volatile("cp.async.commit_group;" ::: "memory")
#define CP_WAIT0()   asm volatile("cp.async.wait_group 0;" ::: "memory")

// ======================= generic fp32 GEMM (small mats) =====================
// OUTH: write __half output (for U tiles feeding the fp16 MMA).
template <int ACT, int ADD, int OUTH>
__global__ void __launch_bounds__(256) gemm_kernel(
    const float* __restrict__ A, const float* __restrict__ B,
    const float* __restrict__ bias, const float* __restrict__ addsrc,
    void* __restrict__ Cv, int M, int N, int K)
{
    __shared__ float As[16][64];
    __shared__ float Bs[16][64];
    const int bm = blockIdx.y * 64, bn = blockIdx.x * 64;
    const int tid = threadIdx.x;
    const int ty = tid >> 4, tx = tid & 15;

    float acc[4][4] = {};
    for (int k0 = 0; k0 < K; k0 += 16) {
#pragma unroll
        for (int l = 0; l < 4; ++l) {
            int idx = tid + l * 256;
            int r = idx >> 4, c = idx & 15;
            int gr = bm + r;
            As[c][r] = (gr < M) ? A[(size_t)gr * K + k0 + c] : 0.0f;
        }
#pragma unroll
        for (int l = 0; l < 4; ++l) {
            int idx = tid + l * 256;
            int r = idx >> 6, c = idx & 63;
            Bs[r][c] = B[(size_t)(k0 + r) * N + bn + c];
        }
        __syncthreads();
#pragma unroll
        for (int kk = 0; kk < 16; ++kk) {
            float ra[4], rb[4];
#pragma unroll
            for (int a = 0; a < 4; ++a) ra[a] = As[kk][ty * 4 + a];
#pragma unroll
            for (int b = 0; b < 4; ++b) rb[b] = Bs[kk][tx * 4 + b];
#pragma unroll
            for (int a = 0; a < 4; ++a)
#pragma unroll
                for (int b = 0; b < 4; ++b)
                    acc[a][b] = fmaf(ra[a], rb[b], acc[a][b]);
        }
        __syncthreads();
    }
#pragma unroll
    for (int a = 0; a < 4; ++a) {
        int m = bm + ty * 4 + a;
        if (m >= M) continue;
#pragma unroll
        for (int b = 0; b < 4; ++b) {
            int n = bn + tx * 4 + b;
            float v = acc[a][b] + bias[n];
            if (ACT) v = softplusf(v);
            if (ADD) v += addsrc[(size_t)m * N + n];
            if (OUTH)
                ((__half*)Cv)[(size_t)m * N + n] = __float2half_rn(v);
            else
                ((float*)Cv)[(size_t)m * N + n] = v;
        }
    }
}

// ---- weight transpose [128,5120] -> [5120,128], converted to fp16 ---------
__global__ void transpose_kernel(const float* __restrict__ W, __half* __restrict__ WT)
{
    __shared__ float t[32][33];
    const int j0 = blockIdx.x * 32, d0 = blockIdx.y * 32;
    for (int r = threadIdx.y; r < 32; r += 8)
        t[r][threadIdx.x] = W[(size_t)(d0 + r) * 5120 + j0 + threadIdx.x];
    __syncthreads();
    for (int r = threadIdx.y; r < 32; r += 8)
        WT[(size_t)(j0 + r) * 128 + d0 + threadIdx.x] =
            __float2half_rn(t[threadIdx.x][r]);
}

// ---------------- spherical harmonics per edge -----------------------------
__global__ void sh_kernel(const float* __restrict__ ev, int E)
{
    int e = blockIdx.x * blockDim.x + threadIdx.x;
    if (e >= E) return;
    float x = ev[e * 3 + 0], y = ev[e * 3 + 1], z = ev[e * 3 + 2];
    float rn = rsqrtf(x * x + y * y + z * z);
    x *= rn; y *= rn; z *= rn;
    const float s3 = 1.7320508075688772f;
    const float s5 = 2.2360679774997896f;
    float* o = g_shb + (size_t)e * 8;
    o[0] = s3 * x;
    o[1] = s3 * y;
    o[2] = s3 * z;
    o[3] = s5 * s3 * x * z;
    o[4] = s5 * s3 * x * y;
    o[5] = s5 * (y * y - 0.5f * (x * x + z * z));
    o[6] = s5 * s3 * y * z;
    o[7] = s5 * (s3 * 0.5f) * (z * z - x * x);
}

__global__ void zero_kernel(int Nn)
{
    int t = blockIdx.x * blockDim.x + threadIdx.x;
    int gs = gridDim.x * blockDim.x;
    for (int i = t; i < Nn * 128; i += gs) g_h1[i] = 0.0f;
    for (int i = t; i < Nn * 64;  i += gs) g_h2[i] = 0.0f;
    for (int i = t; i < Nn;       i += gs) g_cnt[i] = 0.0f;
}

// ======================= fp16 mma.sync fused message pass ====================
// 128 edges/CTA, 512 threads, 16 warps: warp = (mtile = wid>>1, nhalf = wid&1).
// Per chunk ch (80): P[128,64] = U[128,128]@Wch[64,128]^T + bias via fp16
// m16n8k16 MMA (A in registers as half2, W cp.async-staged in padded smem),
// folded into per-edge accumulators by the S contraction, scattered atomically.
//
// smem bytes: sW0 @0 (64 rows x 68 half2 = 17408), sW1 @17408,
//             sS @34816 (128x81 fp32 = 41472), sBias @76288 (5120 fp32).
#define OFF_W0   0
#define OFF_W1   17408
#define OFF_SS   34816
#define OFF_BIAS 76288
#define SMEM_MSG_B 96768
#define WROW 68   // half2 units per W smem row (64 data + 4 pad)

__device__ __forceinline__ void fill_W_async(char* smem, uint32_t bufoff,
    const __half* __restrict__ WT, int ch, int tid)
{
#pragma unroll
    for (int i = 0; i < 2; ++i) {
        int idx = tid + i * 512;          // 0..1023
        int row = idx >> 4;               // n: 0..63
        int q   = idx & 15;               // 16B chunk within row
        const __half* src = WT + (size_t)(ch * 64 + row) * 128 + q * 8;
        uint32_t dst = smem_u32(smem + bufoff + (row * WROW + q * 4) * 4);
        CP_ASYNC16(dst, src);
    }
}

template <int PASS>
__global__ void __launch_bounds__(512, 1) msg_mma_kernel(
    const int* __restrict__ ei, const __half* __restrict__ Uh,
    const __half* __restrict__ WT, const float* __restrict__ B2, int E)
{
    extern __shared__ __align__(16) char smem[];
    float* sS    = reinterpret_cast<float*>(smem + OFF_SS);     // [128][81]
    float* sBias = reinterpret_cast<float*>(smem + OFF_BIAS);   // [5120]

    const int tid = threadIdx.x;
    const int wid = tid >> 5, lane = tid & 31;
    const int mt = wid >> 1, nh = wid & 1;
    const int lq = lane >> 2, la = lane & 3;
    const int e0 = blockIdx.x * 128;
    const int ne = min(128, E - e0);
    const int r0 = mt * 16 + lq, r1 = r0 + 8;
    const bool v0 = r0 < ne, v1 = r1 < ne;

    // kick off W chunk 0 load
    fill_W_async(smem, OFF_W0, WT, 0, tid);
    CP_COMMIT();

    // bias to smem
    for (int i = tid; i < 5120; i += 512) sBias[i] = B2[i];

    // ---- S tile ----
    if (PASS == 1) {
        for (int idx = tid; idx < 128 * 64; idx += 512) {
            int e = idx >> 6, i = idx & 63;
            float v = 0.0f;
            if (e < ne) {
                int dst = ei[E + e0 + e];
                v = g_h[(size_t)dst * 64 + i];
            }
            sS[e * 81 + i] = v;
        }
    } else {
        for (int idx = tid; idx < 128 * 80; idx += 512) {
            int e = idx / 80, j = idx - e * 80;
            float v = 0.0f;
            if (e < ne) {
                int dst = ei[E + e0 + e];
                const float* he = g_h1 + (size_t)dst * 128;
                if (j < 64) {
                    v = he[j];
                } else if (j < 72) {
                    int i = j - 64; float p = 0.0f;
#pragma unroll
                    for (int m = 0; m < 3; ++m)
                        p += he[64 + i * 3 + m] * g_shb[(size_t)(e0 + e) * 8 + m];
                    v = p * 0.5773502691896258f;
                } else {
                    int i = j - 72; float p = 0.0f;
#pragma unroll
                    for (int m = 0; m < 5; ++m)
                        p += he[88 + i * 5 + m] * g_shb[(size_t)(e0 + e) * 8 + 3 + m];
                    v = p * 0.4472135954999579f;
                }
            }
            sS[e * 81 + j] = v;
        }
    }

    // ---- A registers: U rows r0, r1 as half2 (m16n8k16 A-fragment) ----
    // a0: (r0, k=2la..2la+1), a1: (r1, same), a2: (r0, k+8), a3: (r1, k+8)
    uint32_t A0[8], A1[8], A2[8], A3[8];
    {
        const uint32_t* u0 = reinterpret_cast<const uint32_t*>(
            Uh + (size_t)(e0 + (v0 ? r0 : 0)) * 128) + la;
        const uint32_t* u1 = reinterpret_cast<const uint32_t*>(
            Uh + (size_t)(e0 + (v1 ? r1 : 0)) * 128) + la;
#pragma unroll
        for (int ks = 0; ks < 8; ++ks) {
            A0[ks] = v0 ? u0[ks * 8]     : 0u;
            A2[ks] = v0 ? u0[ks * 8 + 4] : 0u;
            A1[ks] = v1 ? u1[ks * 8]     : 0u;
            A3[ks] = v1 ? u1[ks * 8 + 4] : 0u;
        }
    }

    float accA[4][4];   // [ntl][{r0c0,r0c1,r1c0,r1c1}]
    float accB[4], accC[4];
#pragma unroll
    for (int i = 0; i < 4; ++i) {
#pragma unroll
        for (int j = 0; j < 4; ++j) accA[i][j] = 0.0f;
        accB[i] = 0.0f; accC[i] = 0.0f;
    }

    CP_WAIT0();
    __syncthreads();

    for (int ch = 0; ch < 80; ++ch) {
        const uint32_t* wb = reinterpret_cast<const uint32_t*>(
            smem + ((ch & 1) ? OFF_W1 : OFF_W0));
        if (ch + 1 < 80) {
            fill_W_async(smem, (ch & 1) ? OFF_W0 : OFF_W1, WT, ch + 1, tid);
            CP_COMMIT();
        }

        // init c from bias
        float c[4][4];
#pragma unroll
        for (int ntl = 0; ntl < 4; ++ntl) {
            const float2 bb = *reinterpret_cast<const float2*>(
                sBias + ch * 64 + (nh * 4 + ntl) * 8 + la * 2);
            c[ntl][0] = bb.x; c[ntl][1] = bb.y;
            c[ntl][2] = bb.x; c[ntl][3] = bb.y;
        }

        // B-fragment: b0 = W[n = nt*8+lq][k = ks*16 + 2la..], b1 = k+8
#pragma unroll
        for (int ks = 0; ks < 8; ++ks) {
#pragma unroll
            for (int ntl = 0; ntl < 4; ++ntl) {
                const int nrow = (nh * 4 + ntl) * 8 + lq;
                uint32_t b0 = wb[nrow * WROW + ks * 8 + la];
                uint32_t b1 = wb[nrow * WROW + ks * 8 + la + 4];
                mma_f16_m16n8k16(c[ntl], A0[ks], A1[ks], A2[ks], A3[ks], b0, b1);
            }
        }

        // fold with S
        if (PASS == 2 || ch < 64) {
            float s0 = sS[r0 * 81 + ch];
            float s1 = sS[r1 * 81 + ch];
#pragma unroll
            for (int ntl = 0; ntl < 4; ++ntl) {
                accA[ntl][0] = fmaf(s0, c[ntl][0], accA[ntl][0]);
                accA[ntl][1] = fmaf(s0, c[ntl][1], accA[ntl][1]);
                accA[ntl][2] = fmaf(s1, c[ntl][2], accA[ntl][2]);
                accA[ntl][3] = fmaf(s1, c[ntl][3], accA[ntl][3]);
            }
        } else if (ch < 72) {
#pragma unroll
            for (int ntl = 0; ntl < 4; ++ntl) {
                int i = (ch - 64) * 8 + nh * 4 + ntl;
                float s0 = sS[r0 * 81 + i];
                float s1 = sS[r1 * 81 + i];
                accB[0] = fmaf(s0, c[ntl][0], accB[0]);
                accB[1] = fmaf(s0, c[ntl][1], accB[1]);
                accB[2] = fmaf(s1, c[ntl][2], accB[2]);
                accB[3] = fmaf(s1, c[ntl][3], accB[3]);
            }
        } else {
#pragma unroll
            for (int ntl = 0; ntl < 4; ++ntl) {
                int i = (ch - 72) * 8 + nh * 4 + ntl;
                float s0 = sS[r0 * 81 + i];
                float s1 = sS[r1 * 81 + i];
                accC[0] = fmaf(s0, c[ntl][0], accC[0]);
                accC[1] = fmaf(s0, c[ntl][1], accC[1]);
                accC[2] = fmaf(s1, c[ntl][2], accC[2]);
                accC[3] = fmaf(s1, c[ntl][3], accC[3]);
            }
        }

        if (ch + 1 < 80) CP_WAIT0();
        __syncthreads();
    }

    // ---- epilogue scatter ----
#pragma unroll
    for (int e = 0; e < 2; ++e) {
        int r = e ? r1 : r0;
        if (r >= ne) continue;
        int src = ei[e0 + r];
        if (PASS == 1) {
            const float C1 = 0.125f;
            float* d1 = g_h1 + (size_t)src * 128;
#pragma unroll
            for (int ntl = 0; ntl < 4; ++ntl) {
                int col = (nh * 4 + ntl) * 8 + la * 2;
                atomicAdd(d1 + col,     C1 * accA[ntl][e * 2]);
                atomicAdd(d1 + col + 1, C1 * accA[ntl][e * 2 + 1]);
            }
            float sh[8];
#pragma unroll
            for (int m = 0; m < 8; ++m) sh[m] = g_shb[(size_t)(e0 + r) * 8 + m];
#pragma unroll
            for (int b = 0; b < 2; ++b) {
                int k = la * 2 + b;
                float a1v = C1 * accB[e * 2 + b];
                float a2v = C1 * accC[e * 2 + b];
#pragma unroll
                for (int m = 0; m < 3; ++m)
                    atomicAdd(d1 + 64 + k * 3 + m, a1v * sh[m]);
#pragma unroll
                for (int m = 0; m < 5; ++m)
                    atomicAdd(d1 + 88 + k * 5 + m, a2v * sh[3 + m]);
            }
            if (nh == 0 && la == 0) atomicAdd(&g_cnt[src], 1.0f);
        } else {
            const float INV = 0.11180339887498948f;  // 1/sqrt(80)
            float* d2 = g_h2 + (size_t)src * 64;
#pragma unroll
            for (int ntl = 0; ntl < 4; ++ntl) {
                int col = (nh * 4 + ntl) * 8 + la * 2;
                atomicAdd(d2 + col,     INV * accA[ntl][e * 2]);
                atomicAdd(d2 + col + 1, INV * accA[ntl][e * 2 + 1]);
            }
        }
    }
}

// ---------------- finalize / BN / epilogue ----------------------------------
__global__ void h1_finalize_kernel(int Nn)
{
    int t = blockIdx.x * blockDim.x + threadIdx.x;
    int gs = gridDim.x * blockDim.x;
    for (int idx = t; idx < Nn * 128; idx += gs) {
        int n = idx >> 7, c = idx & 127;
        float cnt = fmaxf(g_cnt[n], 1.0f);
        float v = g_h1[idx] / cnt;
        if (c < 64) v += g_h[n * 64 + c];
        g_h1[idx] = v;
    }
}

__global__ void h2_finalize_kernel(int Nn)
{
    int t = blockIdx.x * blockDim.x + threadIdx.x;
    int gs = gridDim.x * blockDim.x;
    for (int idx = t; idx < Nn * 64; idx += gs) {
        int n = idx >> 6;
        g_h2[idx] /= fmaxf(g_cnt[n], 1.0f);
    }
}

__global__ void bn_stats_kernel(int Nn)
{
    __shared__ float rs[256], rs2[256];
    const int c = blockIdx.x;
    float s = 0.0f, s2 = 0.0f;
    for (int n = threadIdx.x; n < Nn; n += 256) {
        float x = g_h2[(size_t)n * 64 + c];
        s += x; s2 += x * x;
    }
    rs[threadIdx.x] = s; rs2[threadIdx.x] = s2;
    __syncthreads();
    for (int off = 128; off > 0; off >>= 1) {
        if (threadIdx.x < off) {
            rs[threadIdx.x]  += rs[threadIdx.x + off];
            rs2[threadIdx.x] += rs2[threadIdx.x + off];
        }
        __syncthreads();
    }
    if (threadIdx.x == 0) {
        float mu = rs[0] / (float)Nn;
        g_mu[c]  = mu;
        g_var[c] = rs2[0] / (float)Nn - mu * mu;
    }
}

__global__ void bn_apply_kernel(const float* __restrict__ gamma,
                                const float* __restrict__ beta, int Nn)
{
    int t = blockIdx.x * blockDim.x + threadIdx.x;
    int gs = gridDim.x * blockDim.x;
    for (int idx = t; idx < Nn * 64; idx += gs) {
        int c = idx & 63;
        float x = (g_h2[idx] - g_mu[c]) * rsqrtf(g_var[c] + 1e-5f) * gamma[c] + beta[c];
        g_sph[idx] = softplusf(x);
    }
}

// ---------------- launch ----------------------------------------------------
extern "C" void kernel_launch(void* const* d_in, const int* in_sizes, int n_in,
                              void* d_out, int out_size)
{
    const float* node_feature = (const float*)d_in[0];
    const int*   edge_index   = (const int*)d_in[1];
    const float* edge_feature = (const float*)d_in[2];
    const float* edge_vec     = (const float*)d_in[3];
    const float* w_node = (const float*)d_in[4];
    const float* b_node = (const float*)d_in[5];
    const float* w_skip = (const float*)d_in[6];
    const float* b_skip = (const float*)d_in[7];
    const float* fc1_w1 = (const float*)d_in[8];
    const float* fc1_b1 = (const float*)d_in[9];
    const float* fc1_w2 = (const float*)d_in[10];
    const float* fc1_b2 = (const float*)d_in[11];
    const float* fc2_w1 = (const float*)d_in[12];
    const float* fc2_b1 = (const float*)d_in[13];
    const float* fc2_w2 = (const float*)d_in[14];
    const float* fc2_b2 = (const float*)d_in[15];
    const float* bn_gamma = (const float*)d_in[16];
    const float* bn_beta  = (const float*)d_in[17];
    const float* w_out = (const float*)d_in[18];
    const float* b_out = (const float*)d_in[19];
    float* out = (float*)d_out;

    const int Nn = in_sizes[0] / 256;   // 10000
    const int E  = in_sizes[2] / 128;   // 40000

    float *p_skip, *p_h, *p_sph;
    __half *p_u1h, *p_u2h, *p_w1t, *p_w2t;
    cudaGetSymbolAddress((void**)&p_skip, g_skip);
    cudaGetSymbolAddress((void**)&p_h,    g_h);
    cudaGetSymbolAddress((void**)&p_u1h,  g_u1h);
    cudaGetSymbolAddress((void**)&p_u2h,  g_u2h);
    cudaGetSymbolAddress((void**)&p_sph,  g_sph);
    cudaGetSymbolAddress((void**)&p_w1t,  g_w1t);
    cudaGetSymbolAddress((void**)&p_w2t,  g_w2t);

    cudaFuncSetAttribute((const void*)msg_mma_kernel<1>,
                         cudaFuncAttributeMaxDynamicSharedMemorySize, SMEM_MSG_B);
    cudaFuncSetAttribute((const void*)msg_mma_kernel<2>,
                         cudaFuncAttributeMaxDynamicSharedMemorySize, SMEM_MSG_B);

    // weight transposes (fp16) + sph harmonics + zero scatter buffers
    transpose_kernel<<<dim3(160, 4), dim3(32, 8)>>>(fc1_w2, p_w1t);
    transpose_kernel<<<dim3(160, 4), dim3(32, 8)>>>(fc2_w2, p_w2t);
    sh_kernel<<<(E + 255) / 256, 256>>>(edge_vec, E);
    zero_kernel<<<256, 256>>>(Nn);

    // node-side GEMMs (fp32 out)
    gemm_kernel<0, 0, 0><<<dim3(4, (Nn + 63) / 64), 256>>>(
        node_feature, w_skip, b_skip, nullptr, p_skip, Nn, 256, 256);
    gemm_kernel<0, 0, 0><<<dim3(1, (Nn + 63) / 64), 256>>>(
        node_feature, w_node, b_node, nullptr, p_h, Nn, 64, 256);

    // edge MLP first layers (softplus, fp16 out for MMA A operand)
    gemm_kernel<1, 0, 1><<<dim3(2, (E + 63) / 64), 256>>>(
        edge_feature, fc1_w1, fc1_b1, nullptr, p_u1h, E, 128, 128);
    gemm_kernel<1, 0, 1><<<dim3(2, (E + 63) / 64), 256>>>(
        edge_feature, fc2_w1, fc2_b1, nullptr, p_u2h, E, 128, 128);

    const int nblk = (E + 127) / 128;
    msg_mma_kernel<1><<<nblk, 512, SMEM_MSG_B>>>(edge_index, p_u1h, p_w1t, fc1_b2, E);
    h1_finalize_kernel<<<256, 256>>>(Nn);
    msg_mma_kernel<2><<<nblk, 512, SMEM_MSG_B>>>(edge_index, p_u2h, p_w2t, fc2_b2, E);
    h2_finalize_kernel<<<256, 256>>>(Nn);

    bn_stats_kernel<<<64, 256>>>(Nn);
    bn_apply_kernel<<<256, 256>>>(bn_gamma, bn_beta, Nn);

    // out = softplus(sph @ w_out + b_out) + skip
    gemm_kernel<1, 1, 0><<<dim3(4, (Nn + 63) / 64), 256>>>(
        p_sph, w_out, b_out, p_skip, out, Nn, 256, 64);
}

// round 7
// speedup vs baseline: 4.4202x; 1.0120x over previous
#include <cuda_runtime.h>
#include <cuda_fp16.h>
#include <math.h>
#include <stdint.h>

// Problem constants: N=10000, E=40000, IN_CH=256, OUT_CH=256,
// EDGE_DIM=128, NS=64, NV=8, WN1=WN2=5120.

#define MAXN 10000
#define MAXE 40000

// ---------------- scratch (static __device__ — no allocations allowed) -----
__device__ float  g_skip[MAXN * 256];
__device__ float  g_h   [MAXN * 64];
__device__ __half g_u1h [MAXE * 128];
__device__ __half g_u2h [MAXE * 128];
__device__ float  g_shb [MAXE * 8];     // sh1 (3) + sh2 (5)
__device__ float  g_h1  [MAXN * 128];
__device__ float  g_cnt [MAXN];
__device__ float  g_h2  [MAXN * 64];
__device__ float  g_mu  [64];
__device__ float  g_var [64];
__device__ float  g_sph [MAXN * 64];
__device__ __half g_w1t [5120 * 128];   // fc1_w2 transposed [5120,128], fp16
__device__ __half g_w2t [5120 * 128];   // fc2_w2 transposed, fp16
__device__ int    g_blkctr[2];          // dynamic work counters (msg1, msg2)

__device__ __forceinline__ float softplusf(float x) {
    return fmaxf(x, 0.0f) + log1pf(expf(-fabsf(x)));
}
__device__ __forceinline__ uint32_t smem_u32(const void* p) {
    uint32_t a;
    asm("{ .reg .u64 t; cvta.to.shared.u64 t, %1; cvt.u32.u64 %0, t; }"
        : "=r"(a) : "l"(p));
    return a;
}
__device__ __forceinline__ void mma_f16_m16n8k16(float c[4],
    uint32_t a0, uint32_t a1, uint32_t a2, uint32_t a3,
    uint32_t b0, uint32_t b1)
{
    asm volatile(
        "mma.sync.aligned.m16n8k16.row.col.f32.f16.f16.f32 "
        "{%0,%1,%2,%3}, {%4,%5,%6,%7}, {%8,%9}, {%0,%1,%2,%3};"
        : "+f"(c[0]), "+f"(c[1]), "+f"(c[2]), "+f"(c[3])
        : "r"(a0), "r"(a1), "r"(a2), "r"(a3), "r"(b0), "r"(b1));
}
#define CP_ASYNC16(dst, src) \
    asm volatile("cp.async.cg.shared.global [%0], [%1], 16;" :: "r"(dst), "l"(src))
#define CP_COMMIT()  asm volatile("cp.async.commit_group;" ::: "memory")
#define CP_WAIT0()   asm volatile("cp.async.wait_group 0;" ::: "memory")

// ======================= generic fp32 GEMM (small mats) =====================
// OUTH: write __half output (for U tiles feeding the fp16 MMA).
template <int ACT, int ADD, int OUTH>
__global__ void __launch_bounds__(256) gemm_kernel(
    const float* __restrict__ A, const float* __restrict__ B,
    const float* __restrict__ bias, const float* __restrict__ addsrc,
    void* __restrict__ Cv, int M, int N, int K)
{
    __shared__ float As[16][64];
    __shared__ float Bs[16][64];
    const int bm = blockIdx.y * 64, bn = blockIdx.x * 64;
    const int tid = threadIdx.x;
    const int ty = tid >> 4, tx = tid & 15;

    float acc[4][4] = {};
    for (int k0 = 0; k0 < K; k0 += 16) {
#pragma unroll
        for (int l = 0; l < 4; ++l) {
            int idx = tid + l * 256;
            int r = idx >> 4, c = idx & 15;
            int gr = bm + r;
            As[c][r] = (gr < M) ? A[(size_t)gr * K + k0 + c] : 0.0f;
        }
#pragma unroll
        for (int l = 0; l < 4; ++l) {
            int idx = tid + l * 256;
            int r = idx >> 6, c = idx & 63;
            Bs[r][c] = B[(size_t)(k0 + r) * N + bn + c];
        }
        __syncthreads();
#pragma unroll
        for (int kk = 0; kk < 16; ++kk) {
            float ra[4], rb[4];
#pragma unroll
            for (int a = 0; a < 4; ++a) ra[a] = As[kk][ty * 4 + a];
#pragma unroll
            for (int b = 0; b < 4; ++b) rb[b] = Bs[kk][tx * 4 + b];
#pragma unroll
            for (int a = 0; a < 4; ++a)
#pragma unroll
                for (int b = 0; b < 4; ++b)
                    acc[a][b] = fmaf(ra[a], rb[b], acc[a][b]);
        }
        __syncthreads();
    }
#pragma unroll
    for (int a = 0; a < 4; ++a) {
        int m = bm + ty * 4 + a;
        if (m >= M) continue;
#pragma unroll
        for (int b = 0; b < 4; ++b) {
            int n = bn + tx * 4 + b;
            float v = acc[a][b] + bias[n];
            if (ACT) v = softplusf(v);
            if (ADD) v += addsrc[(size_t)m * N + n];
            if (OUTH)
                ((__half*)Cv)[(size_t)m * N + n] = __float2half_rn(v);
            else
                ((float*)Cv)[(size_t)m * N + n] = v;
        }
    }
}

// ---- weight transpose [128,5120] -> [5120,128], converted to fp16 ---------
__global__ void transpose_kernel(const float* __restrict__ W, __half* __restrict__ WT)
{
    __shared__ float t[32][33];
    const int j0 = blockIdx.x * 32, d0 = blockIdx.y * 32;
    for (int r = threadIdx.y; r < 32; r += 8)
        t[r][threadIdx.x] = W[(size_t)(d0 + r) * 5120 + j0 + threadIdx.x];
    __syncthreads();
    for (int r = threadIdx.y; r < 32; r += 8)
        WT[(size_t)(j0 + r) * 128 + d0 + threadIdx.x] =
            __float2half_rn(t[threadIdx.x][r]);
}

// ---------------- spherical harmonics per edge -----------------------------
__global__ void sh_kernel(const float* __restrict__ ev, int E)
{
    int e = blockIdx.x * blockDim.x + threadIdx.x;
    if (e >= E) return;
    float x = ev[e * 3 + 0], y = ev[e * 3 + 1], z = ev[e * 3 + 2];
    float rn = rsqrtf(x * x + y * y + z * z);
    x *= rn; y *= rn; z *= rn;
    const float s3 = 1.7320508075688772f;
    const float s5 = 2.2360679774997896f;
    float* o = g_shb + (size_t)e * 8;
    o[0] = s3 * x;
    o[1] = s3 * y;
    o[2] = s3 * z;
    o[3] = s5 * s3 * x * z;
    o[4] = s5 * s3 * x * y;
    o[5] = s5 * (y * y - 0.5f * (x * x + z * z));
    o[6] = s5 * s3 * y * z;
    o[7] = s5 * (s3 * 0.5f) * (z * z - x * x);
}

__global__ void zero_kernel(int Nn)
{
    int t = blockIdx.x * blockDim.x + threadIdx.x;
    int gs = gridDim.x * blockDim.x;
    if (t == 0) { g_blkctr[0] = 0; g_blkctr[1] = 0; }
    for (int i = t; i < Nn * 128; i += gs) g_h1[i] = 0.0f;
    for (int i = t; i < Nn * 64;  i += gs) g_h2[i] = 0.0f;
    for (int i = t; i < Nn;       i += gs) g_cnt[i] = 0.0f;
}

// ======================= fp16 mma.sync fused message pass ====================
// Persistent: 148 CTAs, each dynamically pops 128-edge blocks. Per chunk ch
// (80): P[128,64] = U[128,128]@Wch[64,128]^T + bias via fp16 m16n8k16 MMA
// (A in registers, W cp.async double-buffered in smem), folded into per-edge
// accumulators by the S contraction, scattered atomically.
//
// smem bytes: sW0 @0 (64 rows x 68 half2 = 17408), sW1 @17408,
//             sS @34816 (128x81 fp32 = 41472), sBias @76288 (5120 fp32).
#define OFF_W0   0
#define OFF_W1   17408
#define OFF_SS   34816
#define OFF_BIAS 76288
#define SMEM_MSG_B 96768
#define WROW 68   // half2 units per W smem row (64 data + 4 pad)

__device__ __forceinline__ void fill_W_async(char* smem, uint32_t bufoff,
    const __half* __restrict__ WT, int ch, int tid)
{
#pragma unroll
    for (int i = 0; i < 2; ++i) {
        int idx = tid + i * 512;          // 0..1023
        int row = idx >> 4;               // n: 0..63
        int q   = idx & 15;               // 16B chunk within row
        const __half* src = WT + (size_t)(ch * 64 + row) * 128 + q * 8;
        uint32_t dst = smem_u32(smem + bufoff + (row * WROW + q * 4) * 4);
        CP_ASYNC16(dst, src);
    }
}

template <int PASS>
__global__ void __launch_bounds__(512, 1) msg_mma_kernel(
    const int* __restrict__ ei, const __half* __restrict__ Uh,
    const __half* __restrict__ WT, const float* __restrict__ B2,
    int E, int nblk)
{
    extern __shared__ __align__(16) char smem[];
    float* sS    = reinterpret_cast<float*>(smem + OFF_SS);     // [128][81]
    float* sBias = reinterpret_cast<float*>(smem + OFF_BIAS);   // [5120]
    __shared__ int sblk;

    const int tid = threadIdx.x;
    const int wid = tid >> 5, lane = tid & 31;
    const int mt = wid >> 1, nh = wid & 1;
    const int lq = lane >> 2, la = lane & 3;
    const int r0 = mt * 16 + lq, r1 = r0 + 8;

    // bias to smem once per CTA
    for (int i = tid; i < 5120; i += 512) sBias[i] = B2[i];

    while (true) {
        __syncthreads();   // protect sS/sW reuse + sblk
        if (tid == 0) sblk = atomicAdd(&g_blkctr[PASS - 1], 1);
        __syncthreads();
        const int blk = sblk;
        if (blk >= nblk) break;

        const int e0 = blk * 128;
        const int ne = min(128, E - e0);
        const bool v0 = r0 < ne, v1 = r1 < ne;

        // kick off W chunk 0 load
        fill_W_async(smem, OFF_W0, WT, 0, tid);
        CP_COMMIT();

        // ---- S tile ----
        if (PASS == 1) {
            for (int idx = tid; idx < 128 * 64; idx += 512) {
                int e = idx >> 6, i = idx & 63;
                float v = 0.0f;
                if (e < ne) {
                    int dst = ei[E + e0 + e];
                    v = g_h[(size_t)dst * 64 + i];
                }
                sS[e * 81 + i] = v;
            }
        } else {
            for (int idx = tid; idx < 128 * 80; idx += 512) {
                int e = idx / 80, j = idx - e * 80;
                float v = 0.0f;
                if (e < ne) {
                    int dst = ei[E + e0 + e];
                    const float* he = g_h1 + (size_t)dst * 128;
                    if (j < 64) {
                        v = he[j];
                    } else if (j < 72) {
                        int i = j - 64; float p = 0.0f;
#pragma unroll
                        for (int m = 0; m < 3; ++m)
                            p += he[64 + i * 3 + m] * g_shb[(size_t)(e0 + e) * 8 + m];
                        v = p * 0.5773502691896258f;
                    } else {
                        int i = j - 72; float p = 0.0f;
#pragma unroll
                        for (int m = 0; m < 5; ++m)
                            p += he[88 + i * 5 + m] * g_shb[(size_t)(e0 + e) * 8 + 3 + m];
                        v = p * 0.4472135954999579f;
                    }
                }
                sS[e * 81 + j] = v;
            }
        }

        // ---- A registers: U rows r0, r1 as half2 ----
        uint32_t A0[8], A1[8], A2[8], A3[8];
        {
            const uint32_t* u0 = reinterpret_cast<const uint32_t*>(
                Uh + (size_t)(e0 + (v0 ? r0 : 0)) * 128) + la;
            const uint32_t* u1 = reinterpret_cast<const uint32_t*>(
                Uh + (size_t)(e0 + (v1 ? r1 : 0)) * 128) + la;
#pragma unroll
            for (int ks = 0; ks < 8; ++ks) {
                A0[ks] = v0 ? u0[ks * 8]     : 0u;
                A2[ks] = v0 ? u0[ks * 8 + 4] : 0u;
                A1[ks] = v1 ? u1[ks * 8]     : 0u;
                A3[ks] = v1 ? u1[ks * 8 + 4] : 0u;
            }
        }

        float accA[4][4];   // [ntl][{r0c0,r0c1,r1c0,r1c1}]
        float accB[4], accC[4];
#pragma unroll
        for (int i = 0; i < 4; ++i) {
#pragma unroll
            for (int j = 0; j < 4; ++j) accA[i][j] = 0.0f;
            accB[i] = 0.0f; accC[i] = 0.0f;
        }

        CP_WAIT0();
        __syncthreads();

        for (int ch = 0; ch < 80; ++ch) {
            const uint32_t* wb = reinterpret_cast<const uint32_t*>(
                smem + ((ch & 1) ? OFF_W1 : OFF_W0));
            if (ch + 1 < 80) {
                fill_W_async(smem, (ch & 1) ? OFF_W0 : OFF_W1, WT, ch + 1, tid);
                CP_COMMIT();
            }

            // init c from bias
            float c[4][4];
#pragma unroll
            for (int ntl = 0; ntl < 4; ++ntl) {
                const float2 bb = *reinterpret_cast<const float2*>(
                    sBias + ch * 64 + (nh * 4 + ntl) * 8 + la * 2);
                c[ntl][0] = bb.x; c[ntl][1] = bb.y;
                c[ntl][2] = bb.x; c[ntl][3] = bb.y;
            }

#pragma unroll
            for (int ks = 0; ks < 8; ++ks) {
#pragma unroll
                for (int ntl = 0; ntl < 4; ++ntl) {
                    const int nrow = (nh * 4 + ntl) * 8 + lq;
                    uint32_t b0 = wb[nrow * WROW + ks * 8 + la];
                    uint32_t b1 = wb[nrow * WROW + ks * 8 + la + 4];
                    mma_f16_m16n8k16(c[ntl], A0[ks], A1[ks], A2[ks], A3[ks], b0, b1);
                }
            }

            // fold with S
            if (PASS == 2 || ch < 64) {
                float s0 = sS[r0 * 81 + ch];
                float s1 = sS[r1 * 81 + ch];
#pragma unroll
                for (int ntl = 0; ntl < 4; ++ntl) {
                    accA[ntl][0] = fmaf(s0, c[ntl][0], accA[ntl][0]);
                    accA[ntl][1] = fmaf(s0, c[ntl][1], accA[ntl][1]);
                    accA[ntl][2] = fmaf(s1, c[ntl][2], accA[ntl][2]);
                    accA[ntl][3] = fmaf(s1, c[ntl][3], accA[ntl][3]);
                }
            } else if (ch < 72) {
#pragma unroll
                for (int ntl = 0; ntl < 4; ++ntl) {
                    int i = (ch - 64) * 8 + nh * 4 + ntl;
                    float s0 = sS[r0 * 81 + i];
                    float s1 = sS[r1 * 81 + i];
                    accB[0] = fmaf(s0, c[ntl][0], accB[0]);
                    accB[1] = fmaf(s0, c[ntl][1], accB[1]);
                    accB[2] = fmaf(s1, c[ntl][2], accB[2]);
                    accB[3] = fmaf(s1, c[ntl][3], accB[3]);
                }
            } else {
#pragma unroll
                for (int ntl = 0; ntl < 4; ++ntl) {
                    int i = (ch - 72) * 8 + nh * 4 + ntl;
                    float s0 = sS[r0 * 81 + i];
                    float s1 = sS[r1 * 81 + i];
                    accC[0] = fmaf(s0, c[ntl][0], accC[0]);
                    accC[1] = fmaf(s0, c[ntl][1], accC[1]);
                    accC[2] = fmaf(s1, c[ntl][2], accC[2]);
                    accC[3] = fmaf(s1, c[ntl][3], accC[3]);
                }
            }

            if (ch + 1 < 80) CP_WAIT0();
            __syncthreads();
        }

        // ---- epilogue scatter ----
#pragma unroll
        for (int e = 0; e < 2; ++e) {
            int r = e ? r1 : r0;
            if (r >= ne) continue;
            int src = ei[e0 + r];
            if (PASS == 1) {
                const float C1 = 0.125f;
                float* d1 = g_h1 + (size_t)src * 128;
#pragma unroll
                for (int ntl = 0; ntl < 4; ++ntl) {
                    int col = (nh * 4 + ntl) * 8 + la * 2;
                    atomicAdd(d1 + col,     C1 * accA[ntl][e * 2]);
                    atomicAdd(d1 + col + 1, C1 * accA[ntl][e * 2 + 1]);
                }
                float sh[8];
#pragma unroll
                for (int m = 0; m < 8; ++m) sh[m] = g_shb[(size_t)(e0 + r) * 8 + m];
#pragma unroll
                for (int b = 0; b < 2; ++b) {
                    int k = la * 2 + b;
                    float a1v = C1 * accB[e * 2 + b];
                    float a2v = C1 * accC[e * 2 + b];
#pragma unroll
                    for (int m = 0; m < 3; ++m)
                        atomicAdd(d1 + 64 + k * 3 + m, a1v * sh[m]);
#pragma unroll
                    for (int m = 0; m < 5; ++m)
                        atomicAdd(d1 + 88 + k * 5 + m, a2v * sh[3 + m]);
                }
                if (nh == 0 && la == 0) atomicAdd(&g_cnt[src], 1.0f);
            } else {
                const float INV = 0.11180339887498948f;  // 1/sqrt(80)
                float* d2 = g_h2 + (size_t)src * 64;
#pragma unroll
                for (int ntl = 0; ntl < 4; ++ntl) {
                    int col = (nh * 4 + ntl) * 8 + la * 2;
                    atomicAdd(d2 + col,     INV * accA[ntl][e * 2]);
                    atomicAdd(d2 + col + 1, INV * accA[ntl][e * 2 + 1]);
                }
            }
        }
    }
}

// ---------------- finalize / BN / epilogue ----------------------------------
__global__ void h1_finalize_kernel(int Nn)
{
    int t = blockIdx.x * blockDim.x + threadIdx.x;
    int gs = gridDim.x * blockDim.x;
    for (int idx = t; idx < Nn * 128; idx += gs) {
        int n = idx >> 7, c = idx & 127;
        float cnt = fmaxf(g_cnt[n], 1.0f);
        float v = g_h1[idx] / cnt;
        if (c < 64) v += g_h[n * 64 + c];
        g_h1[idx] = v;
    }
}

__global__ void h2_finalize_kernel(int Nn)
{
    int t = blockIdx.x * blockDim.x + threadIdx.x;
    int gs = gridDim.x * blockDim.x;
    for (int idx = t; idx < Nn * 64; idx += gs) {
        int n = idx >> 6;
        g_h2[idx] /= fmaxf(g_cnt[n], 1.0f);
    }
}

__global__ void bn_stats_kernel(int Nn)
{
    __shared__ float rs[256], rs2[256];
    const int c = blockIdx.x;
    float s = 0.0f, s2 = 0.0f;
    for (int n = threadIdx.x; n < Nn; n += 256) {
        float x = g_h2[(size_t)n * 64 + c];
        s += x; s2 += x * x;
    }
    rs[threadIdx.x] = s; rs2[threadIdx.x] = s2;
    __syncthreads();
    for (int off = 128; off > 0; off >>= 1) {
        if (threadIdx.x < off) {
            rs[threadIdx.x]  += rs[threadIdx.x + off];
            rs2[threadIdx.x] += rs2[threadIdx.x + off];
        }
        __syncthreads();
    }
    if (threadIdx.x == 0) {
        float mu = rs[0] / (float)Nn;
        g_mu[c]  = mu;
        g_var[c] = rs2[0] / (float)Nn - mu * mu;
    }
}

__global__ void bn_apply_kernel(const float* __restrict__ gamma,
                                const float* __restrict__ beta, int Nn)
{
    int t = blockIdx.x * blockDim.x + threadIdx.x;
    int gs = gridDim.x * blockDim.x;
    for (int idx = t; idx < Nn * 64; idx += gs) {
        int c = idx & 63;
        float x = (g_h2[idx] - g_mu[c]) * rsqrtf(g_var[c] + 1e-5f) * gamma[c] + beta[c];
        g_sph[idx] = softplusf(x);
    }
}

// ---------------- launch ----------------------------------------------------
extern "C" void kernel_launch(void* const* d_in, const int* in_sizes, int n_in,
                              void* d_out, int out_size)
{
    const float* node_feature = (const float*)d_in[0];
    const int*   edge_index   = (const int*)d_in[1];
    const float* edge_feature = (const float*)d_in[2];
    const float* edge_vec     = (const float*)d_in[3];
    const float* w_node = (const float*)d_in[4];
    const float* b_node = (const float*)d_in[5];
    const float* w_skip = (const float*)d_in[6];
    const float* b_skip = (const float*)d_in[7];
    const float* fc1_w1 = (const float*)d_in[8];
    const float* fc1_b1 = (const float*)d_in[9];
    const float* fc1_w2 = (const float*)d_in[10];
    const float* fc1_b2 = (const float*)d_in[11];
    const float* fc2_w1 = (const float*)d_in[12];
    const float* fc2_b1 = (const float*)d_in[13];
    const float* fc2_w2 = (const float*)d_in[14];
    const float* fc2_b2 = (const float*)d_in[15];
    const float* bn_gamma = (const float*)d_in[16];
    const float* bn_beta  = (const float*)d_in[17];
    const float* w_out = (const float*)d_in[18];
    const float* b_out = (const float*)d_in[19];
    float* out = (float*)d_out;

    const int Nn = in_sizes[0] / 256;   // 10000
    const int E  = in_sizes[2] / 128;   // 40000

    float *p_skip, *p_h, *p_sph;
    __half *p_u1h, *p_u2h, *p_w1t, *p_w2t;
    cudaGetSymbolAddress((void**)&p_skip, g_skip);
    cudaGetSymbolAddress((void**)&p_h,    g_h);
    cudaGetSymbolAddress((void**)&p_u1h,  g_u1h);
    cudaGetSymbolAddress((void**)&p_u2h,  g_u2h);
    cudaGetSymbolAddress((void**)&p_sph,  g_sph);
    cudaGetSymbolAddress((void**)&p_w1t,  g_w1t);
    cudaGetSymbolAddress((void**)&p_w2t,  g_w2t);

    cudaFuncSetAttribute((const void*)msg_mma_kernel<1>,
                         cudaFuncAttributeMaxDynamicSharedMemorySize, SMEM_MSG_B);
    cudaFuncSetAttribute((const void*)msg_mma_kernel<2>,
                         cudaFuncAttributeMaxDynamicSharedMemorySize, SMEM_MSG_B);

    // weight transposes (fp16) + sph harmonics + zero buffers/counters
    transpose_kernel<<<dim3(160, 4), dim3(32, 8)>>>(fc1_w2, p_w1t);
    transpose_kernel<<<dim3(160, 4), dim3(32, 8)>>>(fc2_w2, p_w2t);
    sh_kernel<<<(E + 255) / 256, 256>>>(edge_vec, E);
    zero_kernel<<<256, 256>>>(Nn);

    // node-side GEMMs (fp32 out)
    gemm_kernel<0, 0, 0><<<dim3(4, (Nn + 63) / 64), 256>>>(
        node_feature, w_skip, b_skip, nullptr, p_skip, Nn, 256, 256);
    gemm_kernel<0, 0, 0><<<dim3(1, (Nn + 63) / 64), 256>>>(
        node_feature, w_node, b_node, nullptr, p_h, Nn, 64, 256);

    // edge MLP first layers (softplus, fp16 out for MMA A operand)
    gemm_kernel<1, 0, 1><<<dim3(2, (E + 63) / 64), 256>>>(
        edge_feature, fc1_w1, fc1_b1, nullptr, p_u1h, E, 128, 128);
    gemm_kernel<1, 0, 1><<<dim3(2, (E + 63) / 64), 256>>>(
        edge_feature, fc2_w1, fc2_b1, nullptr, p_u2h, E, 128, 128);

    const int nblk = (E + 127) / 128;
    const int grid_p = nblk < 148 ? nblk : 148;
    msg_mma_kernel<1><<<grid_p, 512, SMEM_MSG_B>>>(
        edge_index, p_u1h, p_w1t, fc1_b2, E, nblk);
    h1_finalize_kernel<<<256, 256>>>(Nn);
    msg_mma_kernel<2><<<grid_p, 512, SMEM_MSG_B>>>(
        edge_index, p_u2h, p_w2t, fc2_b2, E, nblk);
    h2_finalize_kernel<<<256, 256>>>(Nn);

    bn_stats_kernel<<<64, 256>>>(Nn);
    bn_apply_kernel<<<256, 256>>>(bn_gamma, bn_beta, Nn);

    // out = softplus(sph @ w_out + b_out) + skip
    gemm_kernel<1, 1, 0><<<dim3(4, (Nn + 63) / 64), 256>>>(
        p_sph, w_out, b_out, p_skip, out, Nn, 256, 64);
}

// round 8
// speedup vs baseline: 4.5485x; 1.0290x over previous
#include <cuda_runtime.h>
#include <cuda_fp16.h>
#include <math.h>
#include <stdint.h>

// Problem constants: N=10000, E=40000, IN_CH=256, OUT_CH=256,
// EDGE_DIM=128, NS=64, NV=8, WN1=WN2=5120.

#define MAXN 10000
#define MAXE 40000

// ---------------- scratch (static __device__ — no allocations allowed) -----
__device__ float  g_skip[MAXN * 256];
__device__ float  g_h   [MAXN * 64];
__device__ __half g_u1h [MAXE * 128];
__device__ __half g_u2h [MAXE * 128];
__device__ float  g_shb [MAXE * 8];     // sh1 (3) + sh2 (5)
__device__ float  g_h1  [MAXN * 128];
__device__ float  g_cnt [MAXN];
__device__ float  g_h2  [MAXN * 64];
__device__ float  g_mu  [64];
__device__ float  g_var [64];
__device__ float  g_sph [MAXN * 64];
__device__ __half g_w1t [5120 * 128];   // fc1_w2 transposed [5120,128], fp16
__device__ __half g_w2t [5120 * 128];   // fc2_w2 transposed, fp16

__device__ __forceinline__ float softplusf(float x) {
    return fmaxf(x, 0.0f) + log1pf(expf(-fabsf(x)));
}
__device__ __forceinline__ uint32_t smem_u32(const void* p) {
    uint32_t a;
    asm("{ .reg .u64 t; cvta.to.shared.u64 t, %1; cvt.u32.u64 %0, t; }"
        : "=r"(a) : "l"(p));
    return a;
}
__device__ __forceinline__ void mma_f16_m16n8k16(float c[4],
    uint32_t a0, uint32_t a1, uint32_t a2, uint32_t a3,
    uint32_t b0, uint32_t b1)
{
    asm volatile(
        "mma.sync.aligned.m16n8k16.row.col.f32.f16.f16.f32 "
        "{%0,%1,%2,%3}, {%4,%5,%6,%7}, {%8,%9}, {%0,%1,%2,%3};"
        : "+f"(c[0]), "+f"(c[1]), "+f"(c[2]), "+f"(c[3])
        : "r"(a0), "r"(a1), "r"(a2), "r"(a3), "r"(b0), "r"(b1));
}
#define CP_ASYNC16(dst, src) \
    asm volatile("cp.async.cg.shared.global [%0], [%1], 16;" :: "r"(dst), "l"(src))
#define CP_COMMIT()  asm volatile("cp.async.commit_group;" ::: "memory")
#define CP_WAIT0()   asm volatile("cp.async.wait_group 0;" ::: "memory")

// ======================= generic fp32 GEMM (small mats) =====================
// OUTH: write __half output (for U tiles feeding the fp16 MMA).
template <int ACT, int ADD, int OUTH>
__global__ void __launch_bounds__(256) gemm_kernel(
    const float* __restrict__ A, const float* __restrict__ B,
    const float* __restrict__ bias, const float* __restrict__ addsrc,
    void* __restrict__ Cv, int M, int N, int K)
{
    __shared__ float As[16][64];
    __shared__ float Bs[16][64];
    const int bm = blockIdx.y * 64, bn = blockIdx.x * 64;
    const int tid = threadIdx.x;
    const int ty = tid >> 4, tx = tid & 15;

    float acc[4][4] = {};
    for (int k0 = 0; k0 < K; k0 += 16) {
#pragma unroll
        for (int l = 0; l < 4; ++l) {
            int idx = tid + l * 256;
            int r = idx >> 4, c = idx & 15;
            int gr = bm + r;
            As[c][r] = (gr < M) ? A[(size_t)gr * K + k0 + c] : 0.0f;
        }
#pragma unroll
        for (int l = 0; l < 4; ++l) {
            int idx = tid + l * 256;
            int r = idx >> 6, c = idx & 63;
            Bs[r][c] = B[(size_t)(k0 + r) * N + bn + c];
        }
        __syncthreads();
#pragma unroll
        for (int kk = 0; kk < 16; ++kk) {
            float ra[4], rb[4];
#pragma unroll
            for (int a = 0; a < 4; ++a) ra[a] = As[kk][ty * 4 + a];
#pragma unroll
            for (int b = 0; b < 4; ++b) rb[b] = Bs[kk][tx * 4 + b];
#pragma unroll
            for (int a = 0; a < 4; ++a)
#pragma unroll
                for (int b = 0; b < 4; ++b)
                    acc[a][b] = fmaf(ra[a], rb[b], acc[a][b]);
        }
        __syncthreads();
    }
#pragma unroll
    for (int a = 0; a < 4; ++a) {
        int m = bm + ty * 4 + a;
        if (m >= M) continue;
#pragma unroll
        for (int b = 0; b < 4; ++b) {
            int n = bn + tx * 4 + b;
            float v = acc[a][b] + bias[n];
            if (ACT) v = softplusf(v);
            if (ADD) v += addsrc[(size_t)m * N + n];
            if (OUTH)
                ((__half*)Cv)[(size_t)m * N + n] = __float2half_rn(v);
            else
                ((float*)Cv)[(size_t)m * N + n] = v;
        }
    }
}

// ---- weight transpose [128,5120] -> [5120,128], converted to fp16 ---------
__global__ void transpose_kernel(const float* __restrict__ W, __half* __restrict__ WT)
{
    __shared__ float t[32][33];
    const int j0 = blockIdx.x * 32, d0 = blockIdx.y * 32;
    for (int r = threadIdx.y; r < 32; r += 8)
        t[r][threadIdx.x] = W[(size_t)(d0 + r) * 5120 + j0 + threadIdx.x];
    __syncthreads();
    for (int r = threadIdx.y; r < 32; r += 8)
        WT[(size_t)(j0 + r) * 128 + d0 + threadIdx.x] =
            __float2half_rn(t[threadIdx.x][r]);
}

// ---------------- spherical harmonics per edge -----------------------------
__global__ void sh_kernel(const float* __restrict__ ev, int E)
{
    int e = blockIdx.x * blockDim.x + threadIdx.x;
    if (e >= E) return;
    float x = ev[e * 3 + 0], y = ev[e * 3 + 1], z = ev[e * 3 + 2];
    float rn = rsqrtf(x * x + y * y + z * z);
    x *= rn; y *= rn; z *= rn;
    const float s3 = 1.7320508075688772f;
    const float s5 = 2.2360679774997896f;
    float* o = g_shb + (size_t)e * 8;
    o[0] = s3 * x;
    o[1] = s3 * y;
    o[2] = s3 * z;
    o[3] = s5 * s3 * x * z;
    o[4] = s5 * s3 * x * y;
    o[5] = s5 * (y * y - 0.5f * (x * x + z * z));
    o[6] = s5 * s3 * y * z;
    o[7] = s5 * (s3 * 0.5f) * (z * z - x * x);
}

__global__ void zero_kernel(int Nn)
{
    int t = blockIdx.x * blockDim.x + threadIdx.x;
    int gs = gridDim.x * blockDim.x;
    for (int i = t; i < Nn * 128; i += gs) g_h1[i] = 0.0f;
    for (int i = t; i < Nn * 64;  i += gs) g_h2[i] = 0.0f;
    for (int i = t; i < Nn;       i += gs) g_cnt[i] = 0.0f;
}

// ======================= fp16 mma.sync fused message pass ====================
// 128 edges/CTA, 512 threads, 16 warps: warp = (mtile = wid>>1, nhalf = wid&1).
// Per chunk ch (80): P[128,64] = U[128,128]@Wch[64,128]^T + bias via fp16
// m16n8k16 MMA (A in registers, W cp.async double-buffered in smem with a
// 16B-chunk XOR swizzle making all B LDS bank-conflict-free), folded into
// per-edge accumulators by the S contraction, scattered atomically.
//
// W smem layout: row n = 256B (64 words). 16B chunk q stored at q ^ (n&7).
//   b0 word addr = n*64 + ((2ks  ) ^ (n&7))*4 + la
//   b1 word addr = n*64 + ((2ks+1) ^ (n&7))*4 + la
// Across a warp (fixed ks, la; lq = n&7 varies 0..7) the XOR spans all 8
// 16B-chunks -> 8 distinct bank quads -> with la: all 32 banks. Conflict-free.
//
// smem bytes: sW0 @0 (16384), sW1 @16384, sS @32768 (128x81 fp32 = 41472),
//             sBias @74240 (5120 fp32 = 20480). Total 94720.
#define OFF_W0   0
#define OFF_W1   16384
#define OFF_SS   32768
#define OFF_BIAS 74240
#define SMEM_MSG_B 94720

__device__ __forceinline__ void fill_W_async(char* smem, uint32_t bufoff,
    const __half* __restrict__ WT, int ch, int tid)
{
#pragma unroll
    for (int i = 0; i < 2; ++i) {
        int idx = tid + i * 512;          // 0..1023
        int row = idx >> 4;               // n: 0..63
        int q   = idx & 15;               // 16B chunk within row
        const __half* src = WT + (size_t)(ch * 64 + row) * 128 + q * 8;
        uint32_t dst = smem_u32(smem + bufoff + row * 256 + ((q ^ (row & 7)) * 16));
        CP_ASYNC16(dst, src);
    }
}

template <int PASS>
__global__ void __launch_bounds__(512, 1) msg_mma_kernel(
    const int* __restrict__ ei, const __half* __restrict__ Uh,
    const __half* __restrict__ WT, const float* __restrict__ B2, int E)
{
    extern __shared__ __align__(16) char smem[];
    float* sS    = reinterpret_cast<float*>(smem + OFF_SS);     // [128][81]
    float* sBias = reinterpret_cast<float*>(smem + OFF_BIAS);   // [5120]

    const int tid = threadIdx.x;
    const int wid = tid >> 5, lane = tid & 31;
    const int mt = wid >> 1, nh = wid & 1;
    const int lq = lane >> 2, la = lane & 3;
    const int e0 = blockIdx.x * 128;
    const int ne = min(128, E - e0);
    const int r0 = mt * 16 + lq, r1 = r0 + 8;
    const bool v0 = r0 < ne, v1 = r1 < ne;

    // kick off W chunk 0 load
    fill_W_async(smem, OFF_W0, WT, 0, tid);
    CP_COMMIT();

    // bias to smem
    for (int i = tid; i < 5120; i += 512) sBias[i] = B2[i];

    // ---- S tile ----
    if (PASS == 1) {
        for (int idx = tid; idx < 128 * 64; idx += 512) {
            int e = idx >> 6, i = idx & 63;
            float v = 0.0f;
            if (e < ne) {
                int dst = ei[E + e0 + e];
                v = g_h[(size_t)dst * 64 + i];
            }
            sS[e * 81 + i] = v;
        }
    } else {
        for (int idx = tid; idx < 128 * 80; idx += 512) {
            int e = idx / 80, j = idx - e * 80;
            float v = 0.0f;
            if (e < ne) {
                int dst = ei[E + e0 + e];
                const float* he = g_h1 + (size_t)dst * 128;
                if (j < 64) {
                    v = he[j];
                } else if (j < 72) {
                    int i = j - 64; float p = 0.0f;
#pragma unroll
                    for (int m = 0; m < 3; ++m)
                        p += he[64 + i * 3 + m] * g_shb[(size_t)(e0 + e) * 8 + m];
                    v = p * 0.5773502691896258f;
                } else {
                    int i = j - 72; float p = 0.0f;
#pragma unroll
                    for (int m = 0; m < 5; ++m)
                        p += he[88 + i * 5 + m] * g_shb[(size_t)(e0 + e) * 8 + 3 + m];
                    v = p * 0.4472135954999579f;
                }
            }
            sS[e * 81 + j] = v;
        }
    }

    // ---- A registers: U rows r0, r1 as half2 (m16n8k16 A-fragment) ----
    uint32_t A0[8], A1[8], A2[8], A3[8];
    {
        const uint32_t* u0 = reinterpret_cast<const uint32_t*>(
            Uh + (size_t)(e0 + (v0 ? r0 : 0)) * 128) + la;
        const uint32_t* u1 = reinterpret_cast<const uint32_t*>(
            Uh + (size_t)(e0 + (v1 ? r1 : 0)) * 128) + la;
#pragma unroll
        for (int ks = 0; ks < 8; ++ks) {
            A0[ks] = v0 ? u0[ks * 8]     : 0u;
            A2[ks] = v0 ? u0[ks * 8 + 4] : 0u;
            A1[ks] = v1 ? u1[ks * 8]     : 0u;
            A3[ks] = v1 ? u1[ks * 8 + 4] : 0u;
        }
    }

    float accA[4][4];   // [ntl][{r0c0,r0c1,r1c0,r1c1}]
    float accB[4], accC[4];
#pragma unroll
    for (int i = 0; i < 4; ++i) {
#pragma unroll
        for (int j = 0; j < 4; ++j) accA[i][j] = 0.0f;
        accB[i] = 0.0f; accC[i] = 0.0f;
    }

    CP_WAIT0();
    __syncthreads();

    for (int ch = 0; ch < 80; ++ch) {
        const uint32_t* wb = reinterpret_cast<const uint32_t*>(
            smem + ((ch & 1) ? OFF_W1 : OFF_W0));
        if (ch + 1 < 80) {
            fill_W_async(smem, (ch & 1) ? OFF_W0 : OFF_W1, WT, ch + 1, tid);
            CP_COMMIT();
        }

        // init c from bias
        float c[4][4];
#pragma unroll
        for (int ntl = 0; ntl < 4; ++ntl) {
            const float2 bb = *reinterpret_cast<const float2*>(
                sBias + ch * 64 + (nh * 4 + ntl) * 8 + la * 2);
            c[ntl][0] = bb.x; c[ntl][1] = bb.y;
            c[ntl][2] = bb.x; c[ntl][3] = bb.y;
        }

        // B-fragments from XOR-swizzled smem (conflict-free)
#pragma unroll
        for (int ks = 0; ks < 8; ++ks) {
#pragma unroll
            for (int ntl = 0; ntl < 4; ++ntl) {
                const int nrow = (nh * 4 + ntl) * 8 + lq;
                const int base = nrow * 64;
                uint32_t b0 = wb[base + (((2 * ks)     ^ lq) * 4) + la];
                uint32_t b1 = wb[base + (((2 * ks + 1) ^ lq) * 4) + la];
                mma_f16_m16n8k16(c[ntl], A0[ks], A1[ks], A2[ks], A3[ks], b0, b1);
            }
        }

        // fold with S
        if (PASS == 2 || ch < 64) {
            float s0 = sS[r0 * 81 + ch];
            float s1 = sS[r1 * 81 + ch];
#pragma unroll
            for (int ntl = 0; ntl < 4; ++ntl) {
                accA[ntl][0] = fmaf(s0, c[ntl][0], accA[ntl][0]);
                accA[ntl][1] = fmaf(s0, c[ntl][1], accA[ntl][1]);
                accA[ntl][2] = fmaf(s1, c[ntl][2], accA[ntl][2]);
                accA[ntl][3] = fmaf(s1, c[ntl][3], accA[ntl][3]);
            }
        } else if (ch < 72) {
#pragma unroll
            for (int ntl = 0; ntl < 4; ++ntl) {
                int i = (ch - 64) * 8 + nh * 4 + ntl;
                float s0 = sS[r0 * 81 + i];
                float s1 = sS[r1 * 81 + i];
                accB[0] = fmaf(s0, c[ntl][0], accB[0]);
                accB[1] = fmaf(s0, c[ntl][1], accB[1]);
                accB[2] = fmaf(s1, c[ntl][2], accB[2]);
                accB[3] = fmaf(s1, c[ntl][3], accB[3]);
            }
        } else {
#pragma unroll
            for (int ntl = 0; ntl < 4; ++ntl) {
                int i = (ch - 72) * 8 + nh * 4 + ntl;
                float s0 = sS[r0 * 81 + i];
                float s1 = sS[r1 * 81 + i];
                accC[0] = fmaf(s0, c[ntl][0], accC[0]);
                accC[1] = fmaf(s0, c[ntl][1], accC[1]);
                accC[2] = fmaf(s1, c[ntl][2], accC[2]);
                accC[3] = fmaf(s1, c[ntl][3], accC[3]);
            }
        }

        if (ch + 1 < 80) CP_WAIT0();
        __syncthreads();
    }

    // ---- epilogue scatter ----
#pragma unroll
    for (int e = 0; e < 2; ++e) {
        int r = e ? r1 : r0;
        if (r >= ne) continue;
        int src = ei[e0 + r];
        if (PASS == 1) {
            const float C1 = 0.125f;
            float* d1 = g_h1 + (size_t)src * 128;
#pragma unroll
            for (int ntl = 0; ntl < 4; ++ntl) {
                int col = (nh * 4 + ntl) * 8 + la * 2;
                atomicAdd(d1 + col,     C1 * accA[ntl][e * 2]);
                atomicAdd(d1 + col + 1, C1 * accA[ntl][e * 2 + 1]);
            }
            float sh[8];
#pragma unroll
            for (int m = 0; m < 8; ++m) sh[m] = g_shb[(size_t)(e0 + r) * 8 + m];
#pragma unroll
            for (int b = 0; b < 2; ++b) {
                int k = la * 2 + b;
                float a1v = C1 * accB[e * 2 + b];
                float a2v = C1 * accC[e * 2 + b];
#pragma unroll
                for (int m = 0; m < 3; ++m)
                    atomicAdd(d1 + 64 + k * 3 + m, a1v * sh[m]);
#pragma unroll
                for (int m = 0; m < 5; ++m)
                    atomicAdd(d1 + 88 + k * 5 + m, a2v * sh[3 + m]);
            }
            if (nh == 0 && la == 0) atomicAdd(&g_cnt[src], 1.0f);
        } else {
            const float INV = 0.11180339887498948f;  // 1/sqrt(80)
            float* d2 = g_h2 + (size_t)src * 64;
#pragma unroll
            for (int ntl = 0; ntl < 4; ++ntl) {
                int col = (nh * 4 + ntl) * 8 + la * 2;
                atomicAdd(d2 + col,     INV * accA[ntl][e * 2]);
                atomicAdd(d2 + col + 1, INV * accA[ntl][e * 2 + 1]);
            }
        }
    }
}

// ---------------- finalize / BN / epilogue ----------------------------------
__global__ void h1_finalize_kernel(int Nn)
{
    int t = blockIdx.x * blockDim.x + threadIdx.x;
    int gs = gridDim.x * blockDim.x;
    for (int idx = t; idx < Nn * 128; idx += gs) {
        int n = idx >> 7, c = idx & 127;
        float cnt = fmaxf(g_cnt[n], 1.0f);
        float v = g_h1[idx] / cnt;
        if (c < 64) v += g_h[n * 64 + c];
        g_h1[idx] = v;
    }
}

__global__ void h2_finalize_kernel(int Nn)
{
    int t = blockIdx.x * blockDim.x + threadIdx.x;
    int gs = gridDim.x * blockDim.x;
    for (int idx = t; idx < Nn * 64; idx += gs) {
        int n = idx >> 6;
        g_h2[idx] /= fmaxf(g_cnt[n], 1.0f);
    }
}

__global__ void bn_stats_kernel(int Nn)
{
    __shared__ float rs[256], rs2[256];
    const int c = blockIdx.x;
    float s = 0.0f, s2 = 0.0f;
    for (int n = threadIdx.x; n < Nn; n += 256) {
        float x = g_h2[(size_t)n * 64 + c];
        s += x; s2 += x * x;
    }
    rs[threadIdx.x] = s; rs2[threadIdx.x] = s2;
    __syncthreads();
    for (int off = 128; off > 0; off >>= 1) {
        if (threadIdx.x < off) {
            rs[threadIdx.x]  += rs[threadIdx.x + off];
            rs2[threadIdx.x] += rs2[threadIdx.x + off];
        }
        __syncthreads();
    }
    if (threadIdx.x == 0) {
        float mu = rs[0] / (float)Nn;
        g_mu[c]  = mu;
        g_var[c] = rs2[0] / (float)Nn - mu * mu;
    }
}

__global__ void bn_apply_kernel(const float* __restrict__ gamma,
                                const float* __restrict__ beta, int Nn)
{
    int t = blockIdx.x * blockDim.x + threadIdx.x;
    int gs = gridDim.x * blockDim.x;
    for (int idx = t; idx < Nn * 64; idx += gs) {
        int c = idx & 63;
        float x = (g_h2[idx] - g_mu[c]) * rsqrtf(g_var[c] + 1e-5f) * gamma[c] + beta[c];
        g_sph[idx] = softplusf(x);
    }
}

// ---------------- launch ----------------------------------------------------
extern "C" void kernel_launch(void* const* d_in, const int* in_sizes, int n_in,
                              void* d_out, int out_size)
{
    const float* node_feature = (const float*)d_in[0];
    const int*   edge_index   = (const int*)d_in[1];
    const float* edge_feature = (const float*)d_in[2];
    const float* edge_vec     = (const float*)d_in[3];
    const float* w_node = (const float*)d_in[4];
    const float* b_node = (const float*)d_in[5];
    const float* w_skip = (const float*)d_in[6];
    const float* b_skip = (const float*)d_in[7];
    const float* fc1_w1 = (const float*)d_in[8];
    const float* fc1_b1 = (const float*)d_in[9];
    const float* fc1_w2 = (const float*)d_in[10];
    const float* fc1_b2 = (const float*)d_in[11];
    const float* fc2_w1 = (const float*)d_in[12];
    const float* fc2_b1 = (const float*)d_in[13];
    const float* fc2_w2 = (const float*)d_in[14];
    const float* fc2_b2 = (const float*)d_in[15];
    const float* bn_gamma = (const float*)d_in[16];
    const float* bn_beta  = (const float*)d_in[17];
    const float* w_out = (const float*)d_in[18];
    const float* b_out = (const float*)d_in[19];
    float* out = (float*)d_out;

    const int Nn = in_sizes[0] / 256;   // 10000
    const int E  = in_sizes[2] / 128;   // 40000

    float *p_skip, *p_h, *p_sph;
    __half *p_u1h, *p_u2h, *p_w1t, *p_w2t;
    cudaGetSymbolAddress((void**)&p_skip, g_skip);
    cudaGetSymbolAddress((void**)&p_h,    g_h);
    cudaGetSymbolAddress((void**)&p_u1h,  g_u1h);
    cudaGetSymbolAddress((void**)&p_u2h,  g_u2h);
    cudaGetSymbolAddress((void**)&p_sph,  g_sph);
    cudaGetSymbolAddress((void**)&p_w1t,  g_w1t);
    cudaGetSymbolAddress((void**)&p_w2t,  g_w2t);

    cudaFuncSetAttribute((const void*)msg_mma_kernel<1>,
                         cudaFuncAttributeMaxDynamicSharedMemorySize, SMEM_MSG_B);
    cudaFuncSetAttribute((const void*)msg_mma_kernel<2>,
                         cudaFuncAttributeMaxDynamicSharedMemorySize, SMEM_MSG_B);

    // weight transposes (fp16) + sph harmonics + zero scatter buffers
    transpose_kernel<<<dim3(160, 4), dim3(32, 8)>>>(fc1_w2, p_w1t);
    transpose_kernel<<<dim3(160, 4), dim3(32, 8)>>>(fc2_w2, p_w2t);
    sh_kernel<<<(E + 255) / 256, 256>>>(edge_vec, E);
    zero_kernel<<<256, 256>>>(Nn);

    // node-side GEMMs (fp32 out)
    gemm_kernel<0, 0, 0><<<dim3(4, (Nn + 63) / 64), 256>>>(
        node_feature, w_skip, b_skip, nullptr, p_skip, Nn, 256, 256);
    gemm_kernel<0, 0, 0><<<dim3(1, (Nn + 63) / 64), 256>>>(
        node_feature, w_node, b_node, nullptr, p_h, Nn, 64, 256);

    // edge MLP first layers (softplus, fp16 out for MMA A operand)
    gemm_kernel<1, 0, 1><<<dim3(2, (E + 63) / 64), 256>>>(
        edge_feature, fc1_w1, fc1_b1, nullptr, p_u1h, E, 128, 128);
    gemm_kernel<1, 0, 1><<<dim3(2, (E + 63) / 64), 256>>>(
        edge_feature, fc2_w1, fc2_b1, nullptr, p_u2h, E, 128, 128);

    const int nblk = (E + 127) / 128;
    msg_mma_kernel<1><<<nblk, 512, SMEM_MSG_B>>>(edge_index, p_u1h, p_w1t, fc1_b2, E);
    h1_finalize_kernel<<<256, 256>>>(Nn);
    msg_mma_kernel<2><<<nblk, 512, SMEM_MSG_B>>>(edge_index, p_u2h, p_w2t, fc2_b2, E);
    h2_finalize_kernel<<<256, 256>>>(Nn);

    bn_stats_kernel<<<64, 256>>>(Nn);
    bn_apply_kernel<<<256, 256>>>(bn_gamma, bn_beta, Nn);

    // out = softplus(sph @ w_out + b_out) + skip
    gemm_kernel<1, 1, 0><<<dim3(4, (Nn + 63) / 64), 256>>>(
        p_sph, w_out, b_out, p_skip, out, Nn, 256, 64);
}

// round 9
// speedup vs baseline: 5.1897x; 1.1410x over previous
#include <cuda_runtime.h>
#include <cuda_fp16.h>
#include <math.h>
#include <stdint.h>

// Problem constants: N=10000, E=40000, IN_CH=256, OUT_CH=256,
// EDGE_DIM=128, NS=64, NV=8, WN1=WN2=5120.

#define MAXN 10000
#define MAXE 40000

// ---------------- scratch (static __device__ — no allocations allowed) -----
__device__ float  g_skip[MAXN * 256];
__device__ float  g_h   [MAXN * 64];
__device__ __half g_u1h [MAXE * 128];
__device__ __half g_u2h [MAXE * 128];
__device__ float  g_shb [MAXE * 8];     // sh1 (3) + sh2 (5)
__device__ float  g_h1  [MAXN * 128];
__device__ float  g_cnt [MAXN];
__device__ float  g_h2  [MAXN * 64];
__device__ float  g_mu  [64];
__device__ float  g_var [64];
__device__ float  g_sph [MAXN * 64];
__device__ __half g_w1t [5120 * 128];   // fc1_w2 transposed [5120,128], fp16
__device__ __half g_w2t [5120 * 128];   // fc2_w2 transposed, fp16

__device__ __forceinline__ float softplusf(float x) {
    return fmaxf(x, 0.0f) + log1pf(expf(-fabsf(x)));
}
__device__ __forceinline__ uint32_t smem_u32(const void* p) {
    uint32_t a;
    asm("{ .reg .u64 t; cvta.to.shared.u64 t, %1; cvt.u32.u64 %0, t; }"
        : "=r"(a) : "l"(p));
    return a;
}
__device__ __forceinline__ void mma_f16_m16n8k16(float c[4],
    uint32_t a0, uint32_t a1, uint32_t a2, uint32_t a3,
    uint32_t b0, uint32_t b1)
{
    asm volatile(
        "mma.sync.aligned.m16n8k16.row.col.f32.f16.f16.f32 "
        "{%0,%1,%2,%3}, {%4,%5,%6,%7}, {%8,%9}, {%0,%1,%2,%3};"
        : "+f"(c[0]), "+f"(c[1]), "+f"(c[2]), "+f"(c[3])
        : "r"(a0), "r"(a1), "r"(a2), "r"(a3), "r"(b0), "r"(b1));
}
#define CP_ASYNC16(dst, src) \
    asm volatile("cp.async.cg.shared.global [%0], [%1], 16;" :: "r"(dst), "l"(src))
#define CP_COMMIT()  asm volatile("cp.async.commit_group;" ::: "memory")
#define CP_WAIT0()   asm volatile("cp.async.wait_group 0;" ::: "memory")

// ======================= generic fp32 GEMM (small mats) =====================
// OUTH: write __half output (for U tiles feeding the fp16 MMA).
template <int ACT, int ADD, int OUTH>
__global__ void __launch_bounds__(256) gemm_kernel(
    const float* __restrict__ A, const float* __restrict__ B,
    const float* __restrict__ bias, const float* __restrict__ addsrc,
    void* __restrict__ Cv, int M, int N, int K)
{
    __shared__ float As[16][64];
    __shared__ float Bs[16][64];
    const int bm = blockIdx.y * 64, bn = blockIdx.x * 64;
    const int tid = threadIdx.x;
    const int ty = tid >> 4, tx = tid & 15;

    float acc[4][4] = {};
    for (int k0 = 0; k0 < K; k0 += 16) {
#pragma unroll
        for (int l = 0; l < 4; ++l) {
            int idx = tid + l * 256;
            int r = idx >> 4, c = idx & 15;
            int gr = bm + r;
            As[c][r] = (gr < M) ? A[(size_t)gr * K + k0 + c] : 0.0f;
        }
#pragma unroll
        for (int l = 0; l < 4; ++l) {
            int idx = tid + l * 256;
            int r = idx >> 6, c = idx & 63;
            Bs[r][c] = B[(size_t)(k0 + r) * N + bn + c];
        }
        __syncthreads();
#pragma unroll
        for (int kk = 0; kk < 16; ++kk) {
            float ra[4], rb[4];
#pragma unroll
            for (int a = 0; a < 4; ++a) ra[a] = As[kk][ty * 4 + a];
#pragma unroll
            for (int b = 0; b < 4; ++b) rb[b] = Bs[kk][tx * 4 + b];
#pragma unroll
            for (int a = 0; a < 4; ++a)
#pragma unroll
                for (int b = 0; b < 4; ++b)
                    acc[a][b] = fmaf(ra[a], rb[b], acc[a][b]);
        }
        __syncthreads();
    }
#pragma unroll
    for (int a = 0; a < 4; ++a) {
        int m = bm + ty * 4 + a;
        if (m >= M) continue;
#pragma unroll
        for (int b = 0; b < 4; ++b) {
            int n = bn + tx * 4 + b;
            float v = acc[a][b] + bias[n];
            if (ACT) v = softplusf(v);
            if (ADD) v += addsrc[(size_t)m * N + n];
            if (OUTH)
                ((__half*)Cv)[(size_t)m * N + n] = __float2half_rn(v);
            else
                ((float*)Cv)[(size_t)m * N + n] = v;
        }
    }
}

// ---- weight transpose [128,5120] -> [5120,128], converted to fp16 ---------
__global__ void transpose_kernel(const float* __restrict__ W, __half* __restrict__ WT)
{
    __shared__ float t[32][33];
    const int j0 = blockIdx.x * 32, d0 = blockIdx.y * 32;
    for (int r = threadIdx.y; r < 32; r += 8)
        t[r][threadIdx.x] = W[(size_t)(d0 + r) * 5120 + j0 + threadIdx.x];
    __syncthreads();
    for (int r = threadIdx.y; r < 32; r += 8)
        WT[(size_t)(j0 + r) * 128 + d0 + threadIdx.x] =
            __float2half_rn(t[threadIdx.x][r]);
}

// ---------------- spherical harmonics per edge -----------------------------
__global__ void sh_kernel(const float* __restrict__ ev, int E)
{
    int e = blockIdx.x * blockDim.x + threadIdx.x;
    if (e >= E) return;
    float x = ev[e * 3 + 0], y = ev[e * 3 + 1], z = ev[e * 3 + 2];
    float rn = rsqrtf(x * x + y * y + z * z);
    x *= rn; y *= rn; z *= rn;
    const float s3 = 1.7320508075688772f;
    const float s5 = 2.2360679774997896f;
    float* o = g_shb + (size_t)e * 8;
    o[0] = s3 * x;
    o[1] = s3 * y;
    o[2] = s3 * z;
    o[3] = s5 * s3 * x * z;
    o[4] = s5 * s3 * x * y;
    o[5] = s5 * (y * y - 0.5f * (x * x + z * z));
    o[6] = s5 * s3 * y * z;
    o[7] = s5 * (s3 * 0.5f) * (z * z - x * x);
}

__global__ void zero_kernel(int Nn)
{
    int t = blockIdx.x * blockDim.x + threadIdx.x;
    int gs = gridDim.x * blockDim.x;
    for (int i = t; i < Nn * 128; i += gs) g_h1[i] = 0.0f;
    for (int i = t; i < Nn * 64;  i += gs) g_h2[i] = 0.0f;
    for (int i = t; i < Nn;       i += gs) g_cnt[i] = 0.0f;
}

// ======================= fp16 mma.sync fused message pass ====================
// 96 edges/CTA, 384 threads, 12 warps: warp = (mtile = wid>>1, nhalf = wid&1).
// 40 chunk-PAIRS: each round cp.async-fills 2 W chunks (32KB) into the spare
// buffer while computing the current pair; ONE sync per pair (halved barrier
// overhead). P[96,64] = U@Wch^T + bias via fp16 m16n8k16 (A in registers,
// XOR-swizzled W smem), folded by the S contraction, scattered atomically.
//
// smem bytes: sW0 @0 (32768 = 2 chunks), sW1 @32768 (32768),
//             sS @65536 (96x81 fp32 = 31104), sBias @96640 (20480).
#define EBLK     96
#define NWARP    12
#define NTHR     384
#define OFF_W0   0
#define OFF_W1   32768
#define OFF_SS   65536
#define OFF_BIAS 96640
#define SMEM_MSG_B 117120

// Fill TWO chunks (ch0, ch0+1) into buffer at bufoff (2 x 16KB).
__device__ __forceinline__ void fill_W2_async(char* smem, uint32_t bufoff,
    const __half* __restrict__ WT, int ch0, int tid)
{
    for (int idx = tid; idx < 2048; idx += NTHR) {
        int sub = idx >> 10;              // which chunk of the pair
        int w   = idx & 1023;
        int row = w >> 4;                 // n: 0..63
        int q   = w & 15;                 // 16B chunk within row
        const __half* src = WT + ((size_t)(ch0 + sub) * 64 + row) * 128 + q * 8;
        uint32_t dst = smem_u32(smem + bufoff + sub * 16384 +
                                row * 256 + ((q ^ (row & 7)) * 16));
        CP_ASYNC16(dst, src);
    }
}

template <int PASS>
__global__ void __launch_bounds__(NTHR, 1) msg_mma_kernel(
    const int* __restrict__ ei, const __half* __restrict__ Uh,
    const __half* __restrict__ WT, const float* __restrict__ B2, int E)
{
    extern __shared__ __align__(16) char smem[];
    float* sS    = reinterpret_cast<float*>(smem + OFF_SS);     // [96][81]
    float* sBias = reinterpret_cast<float*>(smem + OFF_BIAS);   // [5120]

    const int tid = threadIdx.x;
    const int wid = tid >> 5, lane = tid & 31;
    const int mt = wid >> 1, nh = wid & 1;
    const int lq = lane >> 2, la = lane & 3;
    const int e0 = blockIdx.x * EBLK;
    const int ne = min(EBLK, E - e0);
    const int r0 = mt * 16 + lq, r1 = r0 + 8;
    const bool v0 = r0 < ne, v1 = r1 < ne;

    // kick off W pair 0 load (chunks 0,1)
    fill_W2_async(smem, OFF_W0, WT, 0, tid);
    CP_COMMIT();

    // bias to smem
    for (int i = tid; i < 5120; i += NTHR) sBias[i] = B2[i];

    // ---- S tile ----
    if (PASS == 1) {
        for (int idx = tid; idx < EBLK * 64; idx += NTHR) {
            int e = idx >> 6, i = idx & 63;
            float v = 0.0f;
            if (e < ne) {
                int dst = ei[E + e0 + e];
                v = g_h[(size_t)dst * 64 + i];
            }
            sS[e * 81 + i] = v;
        }
    } else {
        for (int idx = tid; idx < EBLK * 80; idx += NTHR) {
            int e = idx / 80, j = idx - e * 80;
            float v = 0.0f;
            if (e < ne) {
                int dst = ei[E + e0 + e];
                const float* he = g_h1 + (size_t)dst * 128;
                if (j < 64) {
                    v = he[j];
                } else if (j < 72) {
                    int i = j - 64; float p = 0.0f;
#pragma unroll
                    for (int m = 0; m < 3; ++m)
                        p += he[64 + i * 3 + m] * g_shb[(size_t)(e0 + e) * 8 + m];
                    v = p * 0.5773502691896258f;
                } else {
                    int i = j - 72; float p = 0.0f;
#pragma unroll
                    for (int m = 0; m < 5; ++m)
                        p += he[88 + i * 5 + m] * g_shb[(size_t)(e0 + e) * 8 + 3 + m];
                    v = p * 0.4472135954999579f;
                }
            }
            sS[e * 81 + j] = v;
        }
    }

    // ---- A registers: U rows r0, r1 as half2 (m16n8k16 A-fragment) ----
    uint32_t A0[8], A1[8], A2[8], A3[8];
    {
        const uint32_t* u0 = reinterpret_cast<const uint32_t*>(
            Uh + (size_t)(e0 + (v0 ? r0 : 0)) * 128) + la;
        const uint32_t* u1 = reinterpret_cast<const uint32_t*>(
            Uh + (size_t)(e0 + (v1 ? r1 : 0)) * 128) + la;
#pragma unroll
        for (int ks = 0; ks < 8; ++ks) {
            A0[ks] = v0 ? u0[ks * 8]     : 0u;
            A2[ks] = v0 ? u0[ks * 8 + 4] : 0u;
            A1[ks] = v1 ? u1[ks * 8]     : 0u;
            A3[ks] = v1 ? u1[ks * 8 + 4] : 0u;
        }
    }

    float accA[4][4];   // [ntl][{r0c0,r0c1,r1c0,r1c1}]
    float accB[4], accC[4];
#pragma unroll
    for (int i = 0; i < 4; ++i) {
#pragma unroll
        for (int j = 0; j < 4; ++j) accA[i][j] = 0.0f;
        accB[i] = 0.0f; accC[i] = 0.0f;
    }

    CP_WAIT0();
    __syncthreads();

    for (int cp = 0; cp < 40; ++cp) {
        const char* cur = smem + ((cp & 1) ? OFF_W1 : OFF_W0);
        if (cp + 1 < 40) {
            fill_W2_async(smem, (cp & 1) ? OFF_W0 : OFF_W1, WT, 2 * (cp + 1), tid);
            CP_COMMIT();
        }

#pragma unroll
        for (int sub = 0; sub < 2; ++sub) {
            const int ch = 2 * cp + sub;
            const uint32_t* wb = reinterpret_cast<const uint32_t*>(cur + sub * 16384);

            // init c from bias
            float c[4][4];
#pragma unroll
            for (int ntl = 0; ntl < 4; ++ntl) {
                const float2 bb = *reinterpret_cast<const float2*>(
                    sBias + ch * 64 + (nh * 4 + ntl) * 8 + la * 2);
                c[ntl][0] = bb.x; c[ntl][1] = bb.y;
                c[ntl][2] = bb.x; c[ntl][3] = bb.y;
            }

            // B-fragments from XOR-swizzled smem (conflict-free)
#pragma unroll
            for (int ks = 0; ks < 8; ++ks) {
#pragma unroll
                for (int ntl = 0; ntl < 4; ++ntl) {
                    const int nrow = (nh * 4 + ntl) * 8 + lq;
                    const int base = nrow * 64;
                    uint32_t b0 = wb[base + (((2 * ks)     ^ lq) * 4) + la];
                    uint32_t b1 = wb[base + (((2 * ks + 1) ^ lq) * 4) + la];
                    mma_f16_m16n8k16(c[ntl], A0[ks], A1[ks], A2[ks], A3[ks], b0, b1);
                }
            }

            // fold with S
            if (PASS == 2 || ch < 64) {
                float s0 = sS[r0 * 81 + ch];
                float s1 = sS[r1 * 81 + ch];
#pragma unroll
                for (int ntl = 0; ntl < 4; ++ntl) {
                    accA[ntl][0] = fmaf(s0, c[ntl][0], accA[ntl][0]);
                    accA[ntl][1] = fmaf(s0, c[ntl][1], accA[ntl][1]);
                    accA[ntl][2] = fmaf(s1, c[ntl][2], accA[ntl][2]);
                    accA[ntl][3] = fmaf(s1, c[ntl][3], accA[ntl][3]);
                }
            } else if (ch < 72) {
#pragma unroll
                for (int ntl = 0; ntl < 4; ++ntl) {
                    int i = (ch - 64) * 8 + nh * 4 + ntl;
                    float s0 = sS[r0 * 81 + i];
                    float s1 = sS[r1 * 81 + i];
                    accB[0] = fmaf(s0, c[ntl][0], accB[0]);
                    accB[1] = fmaf(s0, c[ntl][1], accB[1]);
                    accB[2] = fmaf(s1, c[ntl][2], accB[2]);
                    accB[3] = fmaf(s1, c[ntl][3], accB[3]);
                }
            } else {
#pragma unroll
                for (int ntl = 0; ntl < 4; ++ntl) {
                    int i = (ch - 72) * 8 + nh * 4 + ntl;
                    float s0 = sS[r0 * 81 + i];
                    float s1 = sS[r1 * 81 + i];
                    accC[0] = fmaf(s0, c[ntl][0], accC[0]);
                    accC[1] = fmaf(s0, c[ntl][1], accC[1]);
                    accC[2] = fmaf(s1, c[ntl][2], accC[2]);
                    accC[3] = fmaf(s1, c[ntl][3], accC[3]);
                }
            }
        }

        if (cp + 1 < 40) CP_WAIT0();
        __syncthreads();
    }

    // ---- epilogue scatter ----
#pragma unroll
    for (int e = 0; e < 2; ++e) {
        int r = e ? r1 : r0;
        if (r >= ne) continue;
        int src = ei[e0 + r];
        if (PASS == 1) {
            const float C1 = 0.125f;
            float* d1 = g_h1 + (size_t)src * 128;
#pragma unroll
            for (int ntl = 0; ntl < 4; ++ntl) {
                int col = (nh * 4 + ntl) * 8 + la * 2;
                atomicAdd(d1 + col,     C1 * accA[ntl][e * 2]);
                atomicAdd(d1 + col + 1, C1 * accA[ntl][e * 2 + 1]);
            }
            float sh[8];
#pragma unroll
            for (int m = 0; m < 8; ++m) sh[m] = g_shb[(size_t)(e0 + r) * 8 + m];
#pragma unroll
            for (int b = 0; b < 2; ++b) {
                int k = la * 2 + b;
                float a1v = C1 * accB[e * 2 + b];
                float a2v = C1 * accC[e * 2 + b];
#pragma unroll
                for (int m = 0; m < 3; ++m)
                    atomicAdd(d1 + 64 + k * 3 + m, a1v * sh[m]);
#pragma unroll
                for (int m = 0; m < 5; ++m)
                    atomicAdd(d1 + 88 + k * 5 + m, a2v * sh[3 + m]);
            }
            if (nh == 0 && la == 0) atomicAdd(&g_cnt[src], 1.0f);
        } else {
            const float INV = 0.11180339887498948f;  // 1/sqrt(80)
            float* d2 = g_h2 + (size_t)src * 64;
#pragma unroll
            for (int ntl = 0; ntl < 4; ++ntl) {
                int col = (nh * 4 + ntl) * 8 + la * 2;
                atomicAdd(d2 + col,     INV * accA[ntl][e * 2]);
                atomicAdd(d2 + col + 1, INV * accA[ntl][e * 2 + 1]);
            }
        }
    }
}

// ---------------- finalize / BN / epilogue ----------------------------------
__global__ void h1_finalize_kernel(int Nn)
{
    int t = blockIdx.x * blockDim.x + threadIdx.x;
    int gs = gridDim.x * blockDim.x;
    for (int idx = t; idx < Nn * 128; idx += gs) {
        int n = idx >> 7, c = idx & 127;
        float cnt = fmaxf(g_cnt[n], 1.0f);
        float v = g_h1[idx] / cnt;
        if (c < 64) v += g_h[n * 64 + c];
        g_h1[idx] = v;
    }
}

__global__ void h2_finalize_kernel(int Nn)
{
    int t = blockIdx.x * blockDim.x + threadIdx.x;
    int gs = gridDim.x * blockDim.x;
    for (int idx = t; idx < Nn * 64; idx += gs) {
        int n = idx >> 6;
        g_h2[idx] /= fmaxf(g_cnt[n], 1.0f);
    }
}

__global__ void bn_stats_kernel(int Nn)
{
    __shared__ float rs[256], rs2[256];
    const int c = blockIdx.x;
    float s = 0.0f, s2 = 0.0f;
    for (int n = threadIdx.x; n < Nn; n += 256) {
        float x = g_h2[(size_t)n * 64 + c];
        s += x; s2 += x * x;
    }
    rs[threadIdx.x] = s; rs2[threadIdx.x] = s2;
    __syncthreads();
    for (int off = 128; off > 0; off >>= 1) {
        if (threadIdx.x < off) {
            rs[threadIdx.x]  += rs[threadIdx.x + off];
            rs2[threadIdx.x] += rs2[threadIdx.x + off];
        }
        __syncthreads();
    }
    if (threadIdx.x == 0) {
        float mu = rs[0] / (float)Nn;
        g_mu[c]  = mu;
        g_var[c] = rs2[0] / (float)Nn - mu * mu;
    }
}

__global__ void bn_apply_kernel(const float* __restrict__ gamma,
                                const float* __restrict__ beta, int Nn)
{
    int t = blockIdx.x * blockDim.x + threadIdx.x;
    int gs = gridDim.x * blockDim.x;
    for (int idx = t; idx < Nn * 64; idx += gs) {
        int c = idx & 63;
        float x = (g_h2[idx] - g_mu[c]) * rsqrtf(g_var[c] + 1e-5f) * gamma[c] + beta[c];
        g_sph[idx] = softplusf(x);
    }
}

// ---------------- launch ----------------------------------------------------
extern "C" void kernel_launch(void* const* d_in, const int* in_sizes, int n_in,
                              void* d_out, int out_size)
{
    const float* node_feature = (const float*)d_in[0];
    const int*   edge_index   = (const int*)d_in[1];
    const float* edge_feature = (const float*)d_in[2];
    const float* edge_vec     = (const float*)d_in[3];
    const float* w_node = (const float*)d_in[4];
    const float* b_node = (const float*)d_in[5];
    const float* w_skip = (const float*)d_in[6];
    const float* b_skip = (const float*)d_in[7];
    const float* fc1_w1 = (const float*)d_in[8];
    const float* fc1_b1 = (const float*)d_in[9];
    const float* fc1_w2 = (const float*)d_in[10];
    const float* fc1_b2 = (const float*)d_in[11];
    const float* fc2_w1 = (const float*)d_in[12];
    const float* fc2_b1 = (const float*)d_in[13];
    const float* fc2_w2 = (const float*)d_in[14];
    const float* fc2_b2 = (const float*)d_in[15];
    const float* bn_gamma = (const float*)d_in[16];
    const float* bn_beta  = (const float*)d_in[17];
    const float* w_out = (const float*)d_in[18];
    const float* b_out = (const float*)d_in[19];
    float* out = (float*)d_out;

    const int Nn = in_sizes[0] / 256;   // 10000
    const int E  = in_sizes[2] / 128;   // 40000

    float *p_skip, *p_h, *p_sph;
    __half *p_u1h, *p_u2h, *p_w1t, *p_w2t;
    cudaGetSymbolAddress((void**)&p_skip, g_skip);
    cudaGetSymbolAddress((void**)&p_h,    g_h);
    cudaGetSymbolAddress((void**)&p_u1h,  g_u1h);
    cudaGetSymbolAddress((void**)&p_u2h,  g_u2h);
    cudaGetSymbolAddress((void**)&p_sph,  g_sph);
    cudaGetSymbolAddress((void**)&p_w1t,  g_w1t);
    cudaGetSymbolAddress((void**)&p_w2t,  g_w2t);

    cudaFuncSetAttribute((const void*)msg_mma_kernel<1>,
                         cudaFuncAttributeMaxDynamicSharedMemorySize, SMEM_MSG_B);
    cudaFuncSetAttribute((const void*)msg_mma_kernel<2>,
                         cudaFuncAttributeMaxDynamicSharedMemorySize, SMEM_MSG_B);

    // weight transposes (fp16) + sph harmonics + zero scatter buffers
    transpose_kernel<<<dim3(160, 4), dim3(32, 8)>>>(fc1_w2, p_w1t);
    transpose_kernel<<<dim3(160, 4), dim3(32, 8)>>>(fc2_w2, p_w2t);
    sh_kernel<<<(E + 255) / 256, 256>>>(edge_vec, E);
    zero_kernel<<<256, 256>>>(Nn);

    // node-side GEMMs (fp32 out)
    gemm_kernel<0, 0, 0><<<dim3(4, (Nn + 63) / 64), 256>>>(
        node_feature, w_skip, b_skip, nullptr, p_skip, Nn, 256, 256);
    gemm_kernel<0, 0, 0><<<dim3(1, (Nn + 63) / 64), 256>>>(
        node_feature, w_node, b_node, nullptr, p_h, Nn, 64, 256);

    // edge MLP first layers (softplus, fp16 out for MMA A operand)
    gemm_kernel<1, 0, 1><<<dim3(2, (E + 63) / 64), 256>>>(
        edge_feature, fc1_w1, fc1_b1, nullptr, p_u1h, E, 128, 128);
    gemm_kernel<1, 0, 1><<<dim3(2, (E + 63) / 64), 256>>>(
        edge_feature, fc2_w1, fc2_b1, nullptr, p_u2h, E, 128, 128);

    const int nblk = (E + EBLK - 1) / EBLK;
    msg_mma_kernel<1><<<nblk, NTHR, SMEM_MSG_B>>>(edge_index, p_u1h, p_w1t, fc1_b2, E);
    h1_finalize_kernel<<<256, 256>>>(Nn);
    msg_mma_kernel<2><<<nblk, NTHR, SMEM_MSG_B>>>(edge_index, p_u2h, p_w2t, fc2_b2, E);
    h2_finalize_kernel<<<256, 256>>>(Nn);

    bn_stats_kernel<<<64, 256>>>(Nn);
    bn_apply_kernel<<<256, 256>>>(bn_gamma, bn_beta, Nn);

    // out = softplus(sph @ w_out + b_out) + skip
    gemm_kernel<1, 1, 0><<<dim3(4, (Nn + 63) / 64), 256>>>(
        p_sph, w_out, b_out, p_skip, out, Nn, 256, 64);
}